// round 12
// baseline (speedup 1.0000x reference)
#include <cuda_runtime.h>
#include <cuda_bf16.h>
#include <cstdint>

#define B_  2
#define S_  2048
#define D_  1024
#define H_  16
#define DH_ 64

// ---------------------------------------------------------------------------
// Scratch (device globals — no allocation allowed)
// ---------------------------------------------------------------------------
__device__ __nv_bfloat16 g_xh[3][(size_t)4096 * 1024]; // bf16-hi of X (q,k,v); [0] reused for ctx
__device__ __nv_bfloat16 g_xl[3][(size_t)4096 * 1024]; // bf16-lo
__device__ __nv_bfloat16 g_wh[4][(size_t)1024 * 1024]; // bf16-hi of W^T (q,k,v,o)
__device__ __nv_bfloat16 g_wl[4][(size_t)1024 * 1024];
// bf16 hi/lo copies of projected Q/K/V in [B,H,S,DH]
__device__ __nv_bfloat16 g_qbh[(size_t)B_ * H_ * S_ * DH_];
__device__ __nv_bfloat16 g_qbl[(size_t)B_ * H_ * S_ * DH_];
__device__ __nv_bfloat16 g_kbh[(size_t)B_ * H_ * S_ * DH_];
__device__ __nv_bfloat16 g_kbl[(size_t)B_ * H_ * S_ * DH_];
__device__ __nv_bfloat16 g_vbh[(size_t)B_ * H_ * S_ * DH_];
__device__ __nv_bfloat16 g_vbl[(size_t)B_ * H_ * S_ * DH_];

// ---------------------------------------------------------------------------
__device__ __forceinline__ uint32_t smem_u32(const void* p) {
    uint32_t a;
    asm("{ .reg .u64 t; cvta.to.shared.u64 t, %1; cvt.u32.u64 %0, t; }" : "=r"(a) : "l"(p));
    return a;
}

#define LDMX4(r, addr) \
    asm volatile("ldmatrix.sync.aligned.m8n8.x4.shared.b16 {%0,%1,%2,%3}, [%4];" \
        : "=r"((r)[0]), "=r"((r)[1]), "=r"((r)[2]), "=r"((r)[3]) : "r"(addr))

#define LDMX4T(r, addr) \
    asm volatile("ldmatrix.sync.aligned.m8n8.x4.trans.shared.b16 {%0,%1,%2,%3}, [%4];" \
        : "=r"((r)[0]), "=r"((r)[1]), "=r"((r)[2]), "=r"((r)[3]) : "r"(addr))

#define MMA_BF16(d, a, b0, b1) \
    asm volatile("mma.sync.aligned.m16n8k16.row.col.f32.bf16.bf16.f32 " \
        "{%0,%1,%2,%3}, {%4,%5,%6,%7}, {%8,%9}, {%0,%1,%2,%3};" \
        : "+f"((d)[0]), "+f"((d)[1]), "+f"((d)[2]), "+f"((d)[3]) \
        : "r"((a)[0]), "r"((a)[1]), "r"((a)[2]), "r"((a)[3]), "r"(b0), "r"(b1))

#define CP_ASYNC16(sa, gp) \
    asm volatile("cp.async.cg.shared.global [%0], [%1], 16;" :: "r"(sa), "l"(gp))
#define CP_COMMIT() asm volatile("cp.async.commit_group;" ::: "memory")
#define CP_WAITN(n) asm volatile("cp.async.wait_group %0;" :: "n"(n) : "memory")

__device__ __forceinline__ void pack_hl(float v0, float v1, uint32_t& hi, uint32_t& lo) {
    __nv_bfloat162 h2 = __floats2bfloat162_rn(v0, v1);
    __nv_bfloat162 l2 = __floats2bfloat162_rn(v0 - __bfloat162float(h2.x),
                                              v1 - __bfloat162float(h2.y));
    hi = *reinterpret_cast<uint32_t*>(&h2);
    lo = *reinterpret_cast<uint32_t*>(&l2);
}

// ---------------------------------------------------------------------------
// Fused prep: blocks [0,12288) = bf16 hi/lo splits of q,k,v;
//             blocks [12288,16384) = transpose+split of the 4 weights.
// ---------------------------------------------------------------------------
struct PrepArgs {
    const float *q, *k, *v, *W0, *W1, *W2, *W3;
    __nv_bfloat16 *xh0, *xl0, *xh1, *xl1, *xh2, *xl2;
};

__global__ __launch_bounds__(256) void prep_kernel(PrepArgs a)
{
    __shared__ float ts[32][33];
    const int bid = blockIdx.x;
    if (bid < 12288) {
        const int z = bid >> 12;
        const int blk = bid & 4095;
        const float* x = (z == 0) ? a.q : (z == 1) ? a.k : a.v;
        __nv_bfloat16* hi = (z == 0) ? a.xh0 : (z == 1) ? a.xh1 : a.xh2;
        __nv_bfloat16* lo = (z == 0) ? a.xl0 : (z == 1) ? a.xl1 : a.xl2;
        int i = blk * 256 + threadIdx.x;
        float4 v4 = ((const float4*)x)[i];
        uint32_t a0, b0, a1, b1;
        pack_hl(v4.x, v4.y, a0, b0);
        pack_hl(v4.z, v4.w, a1, b1);
        ((uint32_t*)hi)[i * 2]     = a0;
        ((uint32_t*)hi)[i * 2 + 1] = a1;
        ((uint32_t*)lo)[i * 2]     = b0;
        ((uint32_t*)lo)[i * 2 + 1] = b1;
    } else {
        const int j = bid - 12288;
        const int z = j >> 10;
        const int r = j & 1023;
        const int kb = (r >> 5) << 5, nb = (r & 31) << 5;
        const float* W = (z == 0) ? a.W0 : (z == 1) ? a.W1 : (z == 2) ? a.W2 : a.W3;
        __nv_bfloat16* th = g_wh[z];
        __nv_bfloat16* tl = g_wl[z];
        int tx = threadIdx.x & 31, ty = threadIdx.x >> 5;
        #pragma unroll
        for (int jj = 0; jj < 4; jj++)
            ts[ty + jj * 8][tx] = W[(size_t)(kb + ty + jj * 8) * 1024 + nb + tx];
        __syncthreads();
        #pragma unroll
        for (int jj = 0; jj < 4; jj++) {
            int n = nb + ty + jj * 8, kk = kb + tx;
            float v = ts[tx][ty + jj * 8];
            __nv_bfloat16 h = __float2bfloat16(v);
            th[(size_t)n * 1024 + kk] = h;
            tl[(size_t)n * 1024 + kk] = __float2bfloat16(v - __bfloat162float(h));
        }
    }
}

// ---------------------------------------------------------------------------
// bf16x3 mma.sync GEMM: ONE 512-thread CTA per SM, CTA tile 128(M) x 256(N),
// K-tile 32, 2-stage. 16 warps (2M x 8N), warp tile 64x32 (~121 regs).
// B's 256-row tile is amortized across all 16 warps -> tensor-bound.
// Row stride 80B (16B-aligned, R5-proven conflict-free for ldmatrix).
// ---------------------------------------------------------------------------
struct GB {
    const __nv_bfloat16 *Ah, *Al, *Bh, *Bl;
    const float* bias;
    float* out; long sB, sS, sH;
    __nv_bfloat16 *oh, *ol;
};
struct GB3 { GB g[3]; };

#define SA_STRIDE 80                        // 64B data + 16B pad (aligned!)
#define A_MAT     (128 * SA_STRIDE)         // 10240
#define B_MAT     (256 * SA_STRIDE)         // 20480
#define STG_BYTES (2 * A_MAT + 2 * B_MAT)   // 61440: Ahi|Alo|Bhi|Blo
#define GEMM_SMEM (2 * STG_BYTES)           // 122880

__global__ __launch_bounds__(512) void gemm_mma_kernel(GB3 P)
{
    const GB p = P.g[blockIdx.z];
    extern __shared__ char sm[];
    const uint32_t sbase = smem_u32(sm);
    const int tid = threadIdx.x, lane = tid & 31, wid = tid >> 5;
    const int wm = wid & 1, wn = wid >> 1;          // 2(M) x 8(N)
    const int m0 = blockIdx.y * 128, n0 = blockIdx.x * 256;

    float acc[4][4][4] = {};                        // 64(M) x 32(N) per warp

    const int arow  = lane & 15;
    const int akoff = (lane >> 4) * 16;
    const int brow  = ((lane >> 4) << 3) | (lane & 7);
    const int bkoff = ((lane >> 3) & 1) * 16;

    // per stage: A 2x(128x4) + B 2x(256x4) = 3072 chunks of 16B; 6/thread
    #define ISSUE(t) do { \
        const int k0i = (t) * 32; \
        const uint32_t sdst = sbase + ((t) & 1) * STG_BYTES; \
        _Pragma("unroll") \
        for (int i = 0; i < 6; i++) { \
            int idx = tid + i * 512; \
            const __nv_bfloat16* gp; uint32_t sa; \
            if (idx < 1024) { \
                int mat = idx >> 9, rem = idx & 511; \
                int row = rem >> 2, c = rem & 3; \
                gp = (mat ? p.Al : p.Ah) + (size_t)(m0 + row) * 1024 + k0i + c * 8; \
                sa = sdst + mat * A_MAT + row * SA_STRIDE + c * 16; \
            } else { \
                int j = idx - 1024; \
                int mat = j >> 10, rem = j & 1023; \
                int row = rem >> 2, c = rem & 3; \
                gp = (mat ? p.Bl : p.Bh) + (size_t)(n0 + row) * 1024 + k0i + c * 8; \
                sa = sdst + 2 * A_MAT + mat * B_MAT + row * SA_STRIDE + c * 16; \
            } \
            CP_ASYNC16(sa, gp); \
        } \
        CP_COMMIT(); \
    } while (0)

    ISSUE(0);
    CP_WAITN(0);
    __syncthreads();

    for (int t = 0; t < 32; t++) {
        if (t < 31) ISSUE(t + 1);

        const uint32_t s0  = sbase + (t & 1) * STG_BYTES;
        const uint32_t pAh = s0;
        const uint32_t pAl = s0 + A_MAT;
        const uint32_t pBh = s0 + 2 * A_MAT;
        const uint32_t pBl = s0 + 2 * A_MAT + B_MAT;

        #pragma unroll
        for (int ks = 0; ks < 2; ks++) {
            uint32_t ah[4][4], al[4][4];
            #pragma unroll
            for (int mf = 0; mf < 4; mf++) {
                uint32_t ra = (uint32_t)(wm * 64 + mf * 16 + arow) * SA_STRIDE + ks * 32 + akoff;
                LDMX4(ah[mf], pAh + ra);
                LDMX4(al[mf], pAl + ra);
            }
            uint32_t bh[2][4], bl[2][4];
            #pragma unroll
            for (int ng = 0; ng < 2; ng++) {
                uint32_t rb = (uint32_t)(wn * 32 + ng * 16 + brow) * SA_STRIDE + ks * 32 + bkoff;
                LDMX4(bh[ng], pBh + rb);
                LDMX4(bl[ng], pBl + rb);
            }
            #pragma unroll
            for (int mf = 0; mf < 4; mf++) {
                #pragma unroll
                for (int nf = 0; nf < 4; nf++) {
                    const uint32_t* bhp = &bh[nf >> 1][(nf & 1) * 2];
                    const uint32_t* blp = &bl[nf >> 1][(nf & 1) * 2];
                    MMA_BF16(acc[mf][nf], ah[mf], bhp[0], bhp[1]);
                    MMA_BF16(acc[mf][nf], ah[mf], blp[0], blp[1]);
                    MMA_BF16(acc[mf][nf], al[mf], bhp[0], bhp[1]);
                }
            }
        }

        if (t < 31) { CP_WAITN(0); __syncthreads(); }
    }

    // ---- epilogue ----
    const int g = lane >> 2, tig = lane & 3;
    const long s2S = DH_, s2H = (long)S_ * DH_, s2B = (long)H_ * S_ * DH_;
    #pragma unroll
    for (int mf = 0; mf < 4; mf++) {
        const int mA = m0 + wm * 64 + mf * 16 + g;
        const int b1 = mA >> 11, s1 = mA & 2047;
        const int b2 = (mA + 8) >> 11, s2 = (mA + 8) & 2047;
        #pragma unroll
        for (int nf = 0; nf < 4; nf++) {
            const int n = n0 + wn * 32 + nf * 8 + tig * 2;
            const int h = n >> 6, d = n & 63;
            const float bv0 = __ldg(p.bias + n), bv1 = __ldg(p.bias + n + 1);
            float p0 = acc[mf][nf][0] + bv0, p1 = acc[mf][nf][1] + bv1;
            float p2 = acc[mf][nf][2] + bv0, p3 = acc[mf][nf][3] + bv1;
            if (p.out) {
                float2 lo_pair, hi_pair;
                lo_pair.x = p0; lo_pair.y = p1;
                hi_pair.x = p2; hi_pair.y = p3;
                *(float2*)(p.out + (size_t)b1 * p.sB + (size_t)s1 * p.sS + (size_t)h * p.sH + d) = lo_pair;
                *(float2*)(p.out + (size_t)b2 * p.sB + (size_t)s2 * p.sS + (size_t)h * p.sH + d) = hi_pair;
            }
            if (p.oh) {
                uint32_t h0, l0, h1, l1;
                pack_hl(p0, p1, h0, l0);
                pack_hl(p2, p3, h1, l1);
                size_t i1 = (size_t)b1 * s2B + (size_t)s1 * s2S + (size_t)h * s2H + d;
                size_t i2 = (size_t)b2 * s2B + (size_t)s2 * s2S + (size_t)h * s2H + d;
                *(uint32_t*)(p.oh + i1) = h0;
                *(uint32_t*)(p.ol + i1) = l0;
                *(uint32_t*)(p.oh + i2) = h1;
                *(uint32_t*)(p.ol + i2) = l1;
            }
        }
    }
    #undef ISSUE
}

// ---------------------------------------------------------------------------
// Tensor-core flash attention (bf16x3, causal, exp2 softmax).
// R10 version — single sync per k-tile. Unchanged.
// ---------------------------------------------------------------------------
#define LOG2E      1.4426950408889634f
#define ASCALE     (0.125f * LOG2E)
#define AMASK      (-10000.0f * LOG2E)

#define QT_BYTES   (128 * 144)
#define KVMAT      (64 * 144)
#define KVSTG      (4 * KVMAT)
#define ATT_SMEM   (2 * QT_BYTES + 2 * KVSTG)   // 110592

__global__ __launch_bounds__(128) void attn_mma_kernel(
    const __nv_bfloat16* __restrict__ Qhg, const __nv_bfloat16* __restrict__ Qlg,
    const __nv_bfloat16* __restrict__ Khg, const __nv_bfloat16* __restrict__ Klg,
    const __nv_bfloat16* __restrict__ Vhg, const __nv_bfloat16* __restrict__ Vlg,
    __nv_bfloat16* __restrict__ Ohg, __nv_bfloat16* __restrict__ Olg)
{
    extern __shared__ char sm[];
    const uint32_t sb  = smem_u32(sm);
    const uint32_t sQh = sb, sQl = sb + QT_BYTES;
    const uint32_t sKV = sb + 2 * QT_BYTES;

    const int tid = threadIdx.x, lane = tid & 31, wid = tid >> 5;
    const int bidx = blockIdx.x;
    const int qblk = (S_ / 128 - 1) - (bidx >> 5);
    const int hb = bidx & 31;
    const int h = hb & 15, b = hb >> 4;
    const int q0 = qblk * 128;
    const int wrow = wid * 32;
    const int g = lane >> 2, tig = lane & 3;

    const size_t hoff = ((size_t)(b * H_ + h) * S_) * DH_;
    const __nv_bfloat16* qh_p = Qhg + hoff + (size_t)q0 * DH_;
    const __nv_bfloat16* ql_p = Qlg + hoff + (size_t)q0 * DH_;
    const __nv_bfloat16* kh_p = Khg + hoff;
    const __nv_bfloat16* kl_p = Klg + hoff;
    const __nv_bfloat16* vh_p = Vhg + hoff;
    const __nv_bfloat16* vl_p = Vlg + hoff;

    #define KV_ISSUE(k0v, st) do { \
        const uint32_t sst = sKV + (st) * KVSTG; \
        _Pragma("unroll") \
        for (int i = 0; i < 16; i++) { \
            int idx = tid + i * 128; \
            int mat = idx >> 9, rem = idx & 511, row = rem >> 3, c = rem & 7; \
            const __nv_bfloat16* gp; uint32_t sa; \
            if (mat == 0)      { gp = kh_p; sa = sst; } \
            else if (mat == 1) { gp = kl_p; sa = sst + KVMAT; } \
            else if (mat == 2) { gp = vh_p; sa = sst + 2 * KVMAT; } \
            else               { gp = vl_p; sa = sst + 3 * KVMAT; } \
            gp += (size_t)((k0v) + row) * 64 + c * 8; \
            sa += row * 144 + c * 16; \
            CP_ASYNC16(sa, gp); \
        } \
        CP_COMMIT(); \
    } while (0)

    const int ktmax = 2 * qblk + 1;

    #pragma unroll
    for (int i = 0; i < 16; i++) {
        int idx = tid + i * 128;
        int mat = idx >> 10, rem = idx & 1023, row = rem >> 3, c = rem & 7;
        const __nv_bfloat16* gp = (mat ? ql_p : qh_p) + row * 64 + c * 8;
        uint32_t sa = (mat ? sQl : sQh) + row * 144 + c * 16;
        CP_ASYNC16(sa, gp);
    }
    KV_ISSUE(0, 0);
    CP_WAITN(0);
    __syncthreads();

    uint32_t qfh[4][2][4], qfl[4][2][4];
    #pragma unroll
    for (int kc = 0; kc < 4; kc++)
        #pragma unroll
        for (int mf = 0; mf < 2; mf++) {
            uint32_t ra = (uint32_t)(wrow + mf * 16 + (lane & 15)) * 144
                          + kc * 32 + (lane >> 4) * 16;
            LDMX4(qfh[kc][mf], sQh + ra);
            LDMX4(qfl[kc][mf], sQl + ra);
        }

    float o[2][8][4] = {};
    float m_run[2][2] = {{-1e30f, -1e30f}, {-1e30f, -1e30f}};
    float l_run[2][2] = {};

    for (int kt = 0; kt <= ktmax; kt++) {
        const int k0 = kt * 64;
        const uint32_t sst = sKV + (kt & 1) * KVSTG;
        const uint32_t sKh = sst, sKl = sst + KVMAT;
        const uint32_t sVh = sst + 2 * KVMAT, sVl = sst + 3 * KVMAT;

        if (kt < ktmax) KV_ISSUE(k0 + 64, (kt + 1) & 1);

        float s[2][8][4] = {};
        #pragma unroll
        for (int kc = 0; kc < 4; kc++) {
            #pragma unroll
            for (int ng = 0; ng < 4; ng++) {
                uint32_t rb = (uint32_t)(ng * 16 + ((lane >> 4) << 3) + (lane & 7)) * 144
                              + kc * 32 + ((lane >> 3) & 1) * 16;
                uint32_t bh[4], bl[4];
                LDMX4(bh, sKh + rb);
                LDMX4(bl, sKl + rb);
                #pragma unroll
                for (int mf = 0; mf < 2; mf++) {
                    MMA_BF16(s[mf][2*ng],   qfh[kc][mf], bh[0], bh[1]);
                    MMA_BF16(s[mf][2*ng],   qfh[kc][mf], bl[0], bl[1]);
                    MMA_BF16(s[mf][2*ng],   qfl[kc][mf], bh[0], bh[1]);
                    MMA_BF16(s[mf][2*ng+1], qfh[kc][mf], bh[2], bh[3]);
                    MMA_BF16(s[mf][2*ng+1], qfh[kc][mf], bl[2], bl[3]);
                    MMA_BF16(s[mf][2*ng+1], qfl[kc][mf], bh[2], bh[3]);
                }
            }
        }

        const bool maskw = (k0 + 63) > (q0 + wrow);
        #pragma unroll
        for (int mf = 0; mf < 2; mf++)
            #pragma unroll
            for (int nf = 0; nf < 8; nf++)
                #pragma unroll
                for (int r = 0; r < 4; r++) {
                    float v = s[mf][nf][r] * ASCALE;
                    if (maskw) {
                        int qi = q0 + wrow + mf * 16 + g + ((r >= 2) ? 8 : 0);
                        int kj = k0 + nf * 8 + tig * 2 + (r & 1);
                        if (kj > qi) v += AMASK;
                    }
                    s[mf][nf][r] = v;
                }

        float alpha[2][2];
        #pragma unroll
        for (int mf = 0; mf < 2; mf++)
            #pragma unroll
            for (int h2 = 0; h2 < 2; h2++) {
                float mx = -1e30f;
                #pragma unroll
                for (int nf = 0; nf < 8; nf++)
                    mx = fmaxf(mx, fmaxf(s[mf][nf][h2*2], s[mf][nf][h2*2+1]));
                mx = fmaxf(mx, __shfl_xor_sync(0xffffffffu, mx, 1));
                mx = fmaxf(mx, __shfl_xor_sync(0xffffffffu, mx, 2));
                float mn = fmaxf(m_run[mf][h2], mx);
                float sum = 0.f;
                #pragma unroll
                for (int nf = 0; nf < 8; nf++) {
                    float p0 = exp2f(s[mf][nf][h2*2]   - mn);
                    float p1 = exp2f(s[mf][nf][h2*2+1] - mn);
                    s[mf][nf][h2*2]   = p0;
                    s[mf][nf][h2*2+1] = p1;
                    sum += p0 + p1;
                }
                sum += __shfl_xor_sync(0xffffffffu, sum, 1);
                sum += __shfl_xor_sync(0xffffffffu, sum, 2);
                float a = exp2f(m_run[mf][h2] - mn);
                alpha[mf][h2] = a;
                m_run[mf][h2] = mn;
                l_run[mf][h2] = l_run[mf][h2] * a + sum;
            }

        #pragma unroll
        for (int mf = 0; mf < 2; mf++)
            #pragma unroll
            for (int nf = 0; nf < 8; nf++) {
                o[mf][nf][0] *= alpha[mf][0];
                o[mf][nf][1] *= alpha[mf][0];
                o[mf][nf][2] *= alpha[mf][1];
                o[mf][nf][3] *= alpha[mf][1];
            }

        #pragma unroll
        for (int kc = 0; kc < 4; kc++) {
            uint32_t ph[2][4], pl[2][4];
            #pragma unroll
            for (int mf = 0; mf < 2; mf++) {
                pack_hl(s[mf][2*kc][0],   s[mf][2*kc][1],   ph[mf][0], pl[mf][0]);
                pack_hl(s[mf][2*kc][2],   s[mf][2*kc][3],   ph[mf][1], pl[mf][1]);
                pack_hl(s[mf][2*kc+1][0], s[mf][2*kc+1][1], ph[mf][2], pl[mf][2]);
                pack_hl(s[mf][2*kc+1][2], s[mf][2*kc+1][3], ph[mf][3], pl[mf][3]);
            }
            #pragma unroll
            for (int ng = 0; ng < 4; ng++) {
                uint32_t rv = (uint32_t)(kc * 16 + ((lane >> 3) & 1) * 8 + (lane & 7)) * 144
                              + ng * 32 + (lane >> 4) * 16;
                uint32_t vh[4], vl[4];
                LDMX4T(vh, sVh + rv);
                LDMX4T(vl, sVl + rv);
                #pragma unroll
                for (int mf = 0; mf < 2; mf++) {
                    MMA_BF16(o[mf][2*ng],   ph[mf], vh[0], vh[1]);
                    MMA_BF16(o[mf][2*ng],   ph[mf], vl[0], vl[1]);
                    MMA_BF16(o[mf][2*ng],   pl[mf], vh[0], vh[1]);
                    MMA_BF16(o[mf][2*ng+1], ph[mf], vh[2], vh[3]);
                    MMA_BF16(o[mf][2*ng+1], ph[mf], vl[2], vl[3]);
                    MMA_BF16(o[mf][2*ng+1], pl[mf], vh[2], vh[3]);
                }
            }
        }

        if (kt < ktmax) { CP_WAITN(0); __syncthreads(); }
    }

    float inv[2][2];
    #pragma unroll
    for (int mf = 0; mf < 2; mf++) {
        inv[mf][0] = 1.f / l_run[mf][0];
        inv[mf][1] = 1.f / l_run[mf][1];
    }
    #pragma unroll
    for (int mf = 0; mf < 2; mf++) {
        const int r0 = q0 + wrow + mf * 16 + g;
        const size_t m1 = (size_t)b * 2048 + r0;
        const size_t m2 = m1 + 8;
        #pragma unroll
        for (int nf = 0; nf < 8; nf++) {
            const int col = h * 64 + nf * 8 + tig * 2;
            uint32_t h0, l0, h1, l1;
            pack_hl(o[mf][nf][0] * inv[mf][0], o[mf][nf][1] * inv[mf][0], h0, l0);
            pack_hl(o[mf][nf][2] * inv[mf][1], o[mf][nf][3] * inv[mf][1], h1, l1);
            *(uint32_t*)(Ohg + m1 * 1024 + col) = h0;
            *(uint32_t*)(Olg + m1 * 1024 + col) = l0;
            *(uint32_t*)(Ohg + m2 * 1024 + col) = h1;
            *(uint32_t*)(Olg + m2 * 1024 + col) = l1;
        }
    }
    #undef KV_ISSUE
}

// ---------------------------------------------------------------------------
extern "C" void kernel_launch(void* const* d_in, const int* in_sizes, int n_in,
                              void* d_out, int out_size)
{
    const float* q  = (const float*)d_in[0];
    const float* k  = (const float*)d_in[1];
    const float* v  = (const float*)d_in[2];
    const float* Wq = (const float*)d_in[4];
    const float* bq = (const float*)d_in[5];
    const float* Wk = (const float*)d_in[6];
    const float* bk = (const float*)d_in[7];
    const float* Wv = (const float*)d_in[8];
    const float* bv = (const float*)d_in[9];
    const float* Wo = (const float*)d_in[10];
    const float* bo = (const float*)d_in[11];

    float* out = (float*)d_out;                       // [B,S,D]
    float* present = out + (size_t)B_ * S_ * D_;      // [B,2,H,S,DH]

    __nv_bfloat16 *xh0, *xl0, *xh1, *xl1, *xh2, *xl2;
    __nv_bfloat16 *wh0, *wl0, *wh1, *wl1, *wh2, *wl2, *wh3, *wl3;
    __nv_bfloat16 *qbh, *qbl, *kbh, *kbl, *vbh, *vbl;
    cudaGetSymbolAddress((void**)&xh0, g_xh);
    cudaGetSymbolAddress((void**)&xl0, g_xl);
    cudaGetSymbolAddress((void**)&wh0, g_wh);
    cudaGetSymbolAddress((void**)&wl0, g_wl);
    cudaGetSymbolAddress((void**)&qbh, g_qbh);
    cudaGetSymbolAddress((void**)&qbl, g_qbl);
    cudaGetSymbolAddress((void**)&kbh, g_kbh);
    cudaGetSymbolAddress((void**)&kbl, g_kbl);
    cudaGetSymbolAddress((void**)&vbh, g_vbh);
    cudaGetSymbolAddress((void**)&vbl, g_vbl);
    const size_t XSZ = (size_t)4096 * 1024, WSZ = (size_t)1024 * 1024;
    xh1 = xh0 + XSZ; xh2 = xh0 + 2 * XSZ;
    xl1 = xl0 + XSZ; xl2 = xl0 + 2 * XSZ;
    wh1 = wh0 + WSZ; wh2 = wh0 + 2 * WSZ; wh3 = wh0 + 3 * WSZ;
    wl1 = wl0 + WSZ; wl2 = wl0 + 2 * WSZ; wl3 = wl0 + 3 * WSZ;

    const long sB_head = (long)H_ * S_ * DH_;
    const long sH_head = (long)S_ * DH_;

    cudaFuncSetAttribute(gemm_mma_kernel, cudaFuncAttributeMaxDynamicSharedMemorySize, GEMM_SMEM);
    cudaFuncSetAttribute(attn_mma_kernel, cudaFuncAttributeMaxDynamicSharedMemorySize, ATT_SMEM);

    // fused prep
    PrepArgs pa = {q, k, v, Wq, Wk, Wv, Wo, xh0, xl0, xh1, xl1, xh2, xl2};
    prep_kernel<<<16384, 256>>>(pa);

    // fused Q/K/V projections (512 threads, CTA 128x256)
    GB3 P;
    P.g[0] = {xh0, xl0, wh0, wl0, bq, nullptr, 0, 0, 0, qbh, qbl};
    P.g[1] = {xh1, xl1, wh1, wl1, bk, present, 2 * sB_head, (long)DH_, sH_head, kbh, kbl};
    P.g[2] = {xh2, xl2, wh2, wl2, bv, present + (size_t)sB_head,
              2 * sB_head, (long)DH_, sH_head, vbh, vbl};
    gemm_mma_kernel<<<dim3(4, 32, 3), 512, GEMM_SMEM>>>(P);

    // attention: ctx written as bf16 hi/lo into g_xh[0]/g_xl[0]
    attn_mma_kernel<<<(S_ / 128) * H_ * B_, 128, ATT_SMEM>>>(
        qbh, qbl, kbh, kbl, vbh, vbl, xh0, xl0);

    // output projection: out = ctx @ Wo + bo
    GB3 PO;
    PO.g[0] = {xh0, xl0, wh3, wl3, bo, out, (long)S_ * D_, (long)D_, (long)DH_,
               nullptr, nullptr};
    PO.g[1] = PO.g[0];
    PO.g[2] = PO.g[0];
    gemm_mma_kernel<<<dim3(4, 32, 1), 512, GEMM_SMEM>>>(PO);
}

// round 13
// speedup vs baseline: 1.0320x; 1.0320x over previous
#include <cuda_runtime.h>
#include <cuda_bf16.h>
#include <cstdint>

#define B_  2
#define S_  2048
#define D_  1024
#define H_  16
#define DH_ 64

// ---------------------------------------------------------------------------
// Scratch (device globals — no allocation allowed)
// ---------------------------------------------------------------------------
__device__ __nv_bfloat16 g_xh[3][(size_t)4096 * 1024]; // bf16-hi of X (q,k,v); [0] reused for ctx
__device__ __nv_bfloat16 g_xl[3][(size_t)4096 * 1024]; // bf16-lo
__device__ __nv_bfloat16 g_wh[4][(size_t)1024 * 1024]; // bf16-hi of W^T (q,k,v,o)
__device__ __nv_bfloat16 g_wl[4][(size_t)1024 * 1024];
// bf16 hi/lo copies of projected Q/K/V in [B,H,S,DH]
__device__ __nv_bfloat16 g_qbh[(size_t)B_ * H_ * S_ * DH_];
__device__ __nv_bfloat16 g_qbl[(size_t)B_ * H_ * S_ * DH_];
__device__ __nv_bfloat16 g_kbh[(size_t)B_ * H_ * S_ * DH_];
__device__ __nv_bfloat16 g_kbl[(size_t)B_ * H_ * S_ * DH_];
__device__ __nv_bfloat16 g_vbh[(size_t)B_ * H_ * S_ * DH_];
__device__ __nv_bfloat16 g_vbl[(size_t)B_ * H_ * S_ * DH_];

// ---------------------------------------------------------------------------
__device__ __forceinline__ uint32_t smem_u32(const void* p) {
    uint32_t a;
    asm("{ .reg .u64 t; cvta.to.shared.u64 t, %1; cvt.u32.u64 %0, t; }" : "=r"(a) : "l"(p));
    return a;
}

#define LDMX4(r, addr) \
    asm volatile("ldmatrix.sync.aligned.m8n8.x4.shared.b16 {%0,%1,%2,%3}, [%4];" \
        : "=r"((r)[0]), "=r"((r)[1]), "=r"((r)[2]), "=r"((r)[3]) : "r"(addr))

#define LDMX4T(r, addr) \
    asm volatile("ldmatrix.sync.aligned.m8n8.x4.trans.shared.b16 {%0,%1,%2,%3}, [%4];" \
        : "=r"((r)[0]), "=r"((r)[1]), "=r"((r)[2]), "=r"((r)[3]) : "r"(addr))

#define MMA_BF16(d, a, b0, b1) \
    asm volatile("mma.sync.aligned.m16n8k16.row.col.f32.bf16.bf16.f32 " \
        "{%0,%1,%2,%3}, {%4,%5,%6,%7}, {%8,%9}, {%0,%1,%2,%3};" \
        : "+f"((d)[0]), "+f"((d)[1]), "+f"((d)[2]), "+f"((d)[3]) \
        : "r"((a)[0]), "r"((a)[1]), "r"((a)[2]), "r"((a)[3]), "r"(b0), "r"(b1))

#define CP_ASYNC16(sa, gp) \
    asm volatile("cp.async.cg.shared.global [%0], [%1], 16;" :: "r"(sa), "l"(gp))
#define CP_COMMIT() asm volatile("cp.async.commit_group;" ::: "memory")
#define CP_WAITN(n) asm volatile("cp.async.wait_group %0;" :: "n"(n) : "memory")

__device__ __forceinline__ void pack_hl(float v0, float v1, uint32_t& hi, uint32_t& lo) {
    __nv_bfloat162 h2 = __floats2bfloat162_rn(v0, v1);
    __nv_bfloat162 l2 = __floats2bfloat162_rn(v0 - __bfloat162float(h2.x),
                                              v1 - __bfloat162float(h2.y));
    hi = *reinterpret_cast<uint32_t*>(&h2);
    lo = *reinterpret_cast<uint32_t*>(&l2);
}

// ---------------------------------------------------------------------------
// Fused prep: blocks [0,12288) = bf16 hi/lo splits of q,k,v;
//             blocks [12288,16384) = transpose+split of the 4 weights.
// ---------------------------------------------------------------------------
struct PrepArgs {
    const float *q, *k, *v, *W0, *W1, *W2, *W3;
    __nv_bfloat16 *xh0, *xl0, *xh1, *xl1, *xh2, *xl2;
};

__global__ __launch_bounds__(256) void prep_kernel(PrepArgs a)
{
    __shared__ float ts[32][33];
    const int bid = blockIdx.x;
    if (bid < 12288) {
        const int z = bid >> 12;
        const int blk = bid & 4095;
        const float* x = (z == 0) ? a.q : (z == 1) ? a.k : a.v;
        __nv_bfloat16* hi = (z == 0) ? a.xh0 : (z == 1) ? a.xh1 : a.xh2;
        __nv_bfloat16* lo = (z == 0) ? a.xl0 : (z == 1) ? a.xl1 : a.xl2;
        int i = blk * 256 + threadIdx.x;
        float4 v4 = ((const float4*)x)[i];
        uint32_t a0, b0, a1, b1;
        pack_hl(v4.x, v4.y, a0, b0);
        pack_hl(v4.z, v4.w, a1, b1);
        ((uint32_t*)hi)[i * 2]     = a0;
        ((uint32_t*)hi)[i * 2 + 1] = a1;
        ((uint32_t*)lo)[i * 2]     = b0;
        ((uint32_t*)lo)[i * 2 + 1] = b1;
    } else {
        const int j = bid - 12288;
        const int z = j >> 10;
        const int r = j & 1023;
        const int kb = (r >> 5) << 5, nb = (r & 31) << 5;
        const float* W = (z == 0) ? a.W0 : (z == 1) ? a.W1 : (z == 2) ? a.W2 : a.W3;
        __nv_bfloat16* th = g_wh[z];
        __nv_bfloat16* tl = g_wl[z];
        int tx = threadIdx.x & 31, ty = threadIdx.x >> 5;
        #pragma unroll
        for (int jj = 0; jj < 4; jj++)
            ts[ty + jj * 8][tx] = W[(size_t)(kb + ty + jj * 8) * 1024 + nb + tx];
        __syncthreads();
        #pragma unroll
        for (int jj = 0; jj < 4; jj++) {
            int n = nb + ty + jj * 8, kk = kb + tx;
            float v = ts[tx][ty + jj * 8];
            __nv_bfloat16 h = __float2bfloat16(v);
            th[(size_t)n * 1024 + kk] = h;
            tl[(size_t)n * 1024 + kk] = __float2bfloat16(v - __bfloat162float(h));
        }
    }
}

// ---------------------------------------------------------------------------
// bf16x3 mma.sync GEMM (R10 config: 8 warps of 64x32, K-tile 32, 2-stage,
// single sync per k-tile). MMA stream reordered PASS-MAJOR so that no two
// consecutive MMAs write the same accumulator (same-acc RAW gap = 16).
// ---------------------------------------------------------------------------
struct GB {
    const __nv_bfloat16 *Ah, *Al, *Bh, *Bl;
    const float* bias;
    float* out; long sB, sS, sH;
    __nv_bfloat16 *oh, *ol;
};
struct GB3 { GB g[3]; };

#define SA_STRIDE 80
#define MAT_BYTES (128 * SA_STRIDE)
#define STG_BYTES (4 * MAT_BYTES)
#define GEMM_SMEM (2 * STG_BYTES)

__global__ __launch_bounds__(256) void gemm_mma_kernel(GB3 P)
{
    const GB p = P.g[blockIdx.z];
    extern __shared__ char sm[];
    const uint32_t sbase = smem_u32(sm);
    const int tid = threadIdx.x, lane = tid & 31, wid = tid >> 5;
    const int wm = wid & 1, wn = wid >> 1;
    const int m0 = blockIdx.y * 128, n0 = blockIdx.x * 128;

    float acc[4][4][4] = {};

    const int arow  = lane & 15;
    const int akoff = (lane >> 4) * 16;
    const int brow  = ((lane >> 4) << 3) | (lane & 7);
    const int bkoff = ((lane >> 3) & 1) * 16;

    #define ISSUE(t) do { \
        const int k0i = (t) * 32; \
        const uint32_t sdst = sbase + ((t) & 1) * STG_BYTES; \
        _Pragma("unroll") \
        for (int i = 0; i < 8; i++) { \
            int idx = tid + i * 256; \
            int mat = idx >> 9, chunk = idx & 511; \
            int row = chunk >> 2, c = chunk & 3; \
            const __nv_bfloat16* gp; \
            if (mat == 0)      gp = p.Ah + (size_t)(m0 + row) * 1024 + k0i + c * 8; \
            else if (mat == 1) gp = p.Al + (size_t)(m0 + row) * 1024 + k0i + c * 8; \
            else if (mat == 2) gp = p.Bh + (size_t)(n0 + row) * 1024 + k0i + c * 8; \
            else               gp = p.Bl + (size_t)(n0 + row) * 1024 + k0i + c * 8; \
            uint32_t sa = sdst + mat * MAT_BYTES + row * SA_STRIDE + c * 16; \
            CP_ASYNC16(sa, gp); \
        } \
        CP_COMMIT(); \
    } while (0)

    ISSUE(0);
    CP_WAITN(0);
    __syncthreads();

    for (int t = 0; t < 32; t++) {
        if (t < 31) ISSUE(t + 1);

        const uint32_t s0  = sbase + (t & 1) * STG_BYTES;
        const uint32_t pAh = s0;
        const uint32_t pAl = s0 + MAT_BYTES;
        const uint32_t pBh = s0 + 2 * MAT_BYTES;
        const uint32_t pBl = s0 + 3 * MAT_BYTES;

        #pragma unroll
        for (int ks = 0; ks < 2; ks++) {
            uint32_t ah[4][4], al[4][4];
            #pragma unroll
            for (int mf = 0; mf < 4; mf++) {
                uint32_t ra = (uint32_t)(wm * 64 + mf * 16 + arow) * SA_STRIDE + ks * 32 + akoff;
                LDMX4(ah[mf], pAh + ra);
                LDMX4(al[mf], pAl + ra);
            }
            uint32_t bh[2][4], bl[2][4];
            #pragma unroll
            for (int ng = 0; ng < 2; ng++) {
                uint32_t rb = (uint32_t)(wn * 32 + ng * 16 + brow) * SA_STRIDE + ks * 32 + bkoff;
                LDMX4(bh[ng], pBh + rb);
                LDMX4(bl[ng], pBl + rb);
            }
            // pass-major: hh sweep, hl sweep, lh sweep (same-acc gap = 16)
            #pragma unroll
            for (int mf = 0; mf < 4; mf++)
                #pragma unroll
                for (int nf = 0; nf < 4; nf++) {
                    const uint32_t* bhp = &bh[nf >> 1][(nf & 1) * 2];
                    MMA_BF16(acc[mf][nf], ah[mf], bhp[0], bhp[1]);
                }
            #pragma unroll
            for (int mf = 0; mf < 4; mf++)
                #pragma unroll
                for (int nf = 0; nf < 4; nf++) {
                    const uint32_t* blp = &bl[nf >> 1][(nf & 1) * 2];
                    MMA_BF16(acc[mf][nf], ah[mf], blp[0], blp[1]);
                }
            #pragma unroll
            for (int mf = 0; mf < 4; mf++)
                #pragma unroll
                for (int nf = 0; nf < 4; nf++) {
                    const uint32_t* bhp = &bh[nf >> 1][(nf & 1) * 2];
                    MMA_BF16(acc[mf][nf], al[mf], bhp[0], bhp[1]);
                }
        }

        if (t < 31) { CP_WAITN(0); __syncthreads(); }
    }

    // ---- epilogue ----
    const int g = lane >> 2, tig = lane & 3;
    const long s2S = DH_, s2H = (long)S_ * DH_, s2B = (long)H_ * S_ * DH_;
    #pragma unroll
    for (int mf = 0; mf < 4; mf++) {
        const int mA = m0 + wm * 64 + mf * 16 + g;
        const int b1 = mA >> 11, s1 = mA & 2047;
        const int b2 = (mA + 8) >> 11, s2 = (mA + 8) & 2047;
        #pragma unroll
        for (int nf = 0; nf < 4; nf++) {
            const int n = n0 + wn * 32 + nf * 8 + tig * 2;
            const int h = n >> 6, d = n & 63;
            const float bv0 = __ldg(p.bias + n), bv1 = __ldg(p.bias + n + 1);
            float p0 = acc[mf][nf][0] + bv0, p1 = acc[mf][nf][1] + bv1;
            float p2 = acc[mf][nf][2] + bv0, p3 = acc[mf][nf][3] + bv1;
            if (p.out) {
                float2 lo_pair, hi_pair;
                lo_pair.x = p0; lo_pair.y = p1;
                hi_pair.x = p2; hi_pair.y = p3;
                *(float2*)(p.out + (size_t)b1 * p.sB + (size_t)s1 * p.sS + (size_t)h * p.sH + d) = lo_pair;
                *(float2*)(p.out + (size_t)b2 * p.sB + (size_t)s2 * p.sS + (size_t)h * p.sH + d) = hi_pair;
            }
            if (p.oh) {
                uint32_t h0, l0, h1, l1;
                pack_hl(p0, p1, h0, l0);
                pack_hl(p2, p3, h1, l1);
                size_t i1 = (size_t)b1 * s2B + (size_t)s1 * s2S + (size_t)h * s2H + d;
                size_t i2 = (size_t)b2 * s2B + (size_t)s2 * s2S + (size_t)h * s2H + d;
                *(uint32_t*)(p.oh + i1) = h0;
                *(uint32_t*)(p.ol + i1) = l0;
                *(uint32_t*)(p.oh + i2) = h1;
                *(uint32_t*)(p.ol + i2) = l1;
            }
        }
    }
    #undef ISSUE
}

// ---------------------------------------------------------------------------
// Tensor-core flash attention (bf16x3, causal, exp2 softmax, single sync per
// k-tile). MMA streams reordered pass-major (same-acc gap >= 4).
// ---------------------------------------------------------------------------
#define LOG2E      1.4426950408889634f
#define ASCALE     (0.125f * LOG2E)
#define AMASK      (-10000.0f * LOG2E)

#define QT_BYTES   (128 * 144)
#define KVMAT      (64 * 144)
#define KVSTG      (4 * KVMAT)
#define ATT_SMEM   (2 * QT_BYTES + 2 * KVSTG)   // 110592

__global__ __launch_bounds__(128) void attn_mma_kernel(
    const __nv_bfloat16* __restrict__ Qhg, const __nv_bfloat16* __restrict__ Qlg,
    const __nv_bfloat16* __restrict__ Khg, const __nv_bfloat16* __restrict__ Klg,
    const __nv_bfloat16* __restrict__ Vhg, const __nv_bfloat16* __restrict__ Vlg,
    __nv_bfloat16* __restrict__ Ohg, __nv_bfloat16* __restrict__ Olg)
{
    extern __shared__ char sm[];
    const uint32_t sb  = smem_u32(sm);
    const uint32_t sQh = sb, sQl = sb + QT_BYTES;
    const uint32_t sKV = sb + 2 * QT_BYTES;

    const int tid = threadIdx.x, lane = tid & 31, wid = tid >> 5;
    const int bidx = blockIdx.x;
    const int qblk = (S_ / 128 - 1) - (bidx >> 5);
    const int hb = bidx & 31;
    const int h = hb & 15, b = hb >> 4;
    const int q0 = qblk * 128;
    const int wrow = wid * 32;
    const int g = lane >> 2, tig = lane & 3;

    const size_t hoff = ((size_t)(b * H_ + h) * S_) * DH_;
    const __nv_bfloat16* qh_p = Qhg + hoff + (size_t)q0 * DH_;
    const __nv_bfloat16* ql_p = Qlg + hoff + (size_t)q0 * DH_;
    const __nv_bfloat16* kh_p = Khg + hoff;
    const __nv_bfloat16* kl_p = Klg + hoff;
    const __nv_bfloat16* vh_p = Vhg + hoff;
    const __nv_bfloat16* vl_p = Vlg + hoff;

    #define KV_ISSUE(k0v, st) do { \
        const uint32_t sst = sKV + (st) * KVSTG; \
        _Pragma("unroll") \
        for (int i = 0; i < 16; i++) { \
            int idx = tid + i * 128; \
            int mat = idx >> 9, rem = idx & 511, row = rem >> 3, c = rem & 7; \
            const __nv_bfloat16* gp; uint32_t sa; \
            if (mat == 0)      { gp = kh_p; sa = sst; } \
            else if (mat == 1) { gp = kl_p; sa = sst + KVMAT; } \
            else if (mat == 2) { gp = vh_p; sa = sst + 2 * KVMAT; } \
            else               { gp = vl_p; sa = sst + 3 * KVMAT; } \
            gp += (size_t)((k0v) + row) * 64 + c * 8; \
            sa += row * 144 + c * 16; \
            CP_ASYNC16(sa, gp); \
        } \
        CP_COMMIT(); \
    } while (0)

    const int ktmax = 2 * qblk + 1;

    #pragma unroll
    for (int i = 0; i < 16; i++) {
        int idx = tid + i * 128;
        int mat = idx >> 10, rem = idx & 1023, row = rem >> 3, c = rem & 7;
        const __nv_bfloat16* gp = (mat ? ql_p : qh_p) + row * 64 + c * 8;
        uint32_t sa = (mat ? sQl : sQh) + row * 144 + c * 16;
        CP_ASYNC16(sa, gp);
    }
    KV_ISSUE(0, 0);
    CP_WAITN(0);
    __syncthreads();

    uint32_t qfh[4][2][4], qfl[4][2][4];
    #pragma unroll
    for (int kc = 0; kc < 4; kc++)
        #pragma unroll
        for (int mf = 0; mf < 2; mf++) {
            uint32_t ra = (uint32_t)(wrow + mf * 16 + (lane & 15)) * 144
                          + kc * 32 + (lane >> 4) * 16;
            LDMX4(qfh[kc][mf], sQh + ra);
            LDMX4(qfl[kc][mf], sQl + ra);
        }

    float o[2][8][4] = {};
    float m_run[2][2] = {{-1e30f, -1e30f}, {-1e30f, -1e30f}};
    float l_run[2][2] = {};

    for (int kt = 0; kt <= ktmax; kt++) {
        const int k0 = kt * 64;
        const uint32_t sst = sKV + (kt & 1) * KVSTG;
        const uint32_t sKh = sst, sKl = sst + KVMAT;
        const uint32_t sVh = sst + 2 * KVMAT, sVl = sst + 3 * KVMAT;

        if (kt < ktmax) KV_ISSUE(k0 + 64, (kt + 1) & 1);

        // ---- S = Q K^T (bf16x3, pass-major: same-acc gap = 4) ----
        float s[2][8][4] = {};
        #pragma unroll
        for (int kc = 0; kc < 4; kc++) {
            #pragma unroll
            for (int ng = 0; ng < 4; ng++) {
                uint32_t rb = (uint32_t)(ng * 16 + ((lane >> 4) << 3) + (lane & 7)) * 144
                              + kc * 32 + ((lane >> 3) & 1) * 16;
                uint32_t bh[4], bl[4];
                LDMX4(bh, sKh + rb);
                LDMX4(bl, sKl + rb);
                #pragma unroll
                for (int mf = 0; mf < 2; mf++) {
                    MMA_BF16(s[mf][2*ng],   qfh[kc][mf], bh[0], bh[1]);
                    MMA_BF16(s[mf][2*ng+1], qfh[kc][mf], bh[2], bh[3]);
                }
                #pragma unroll
                for (int mf = 0; mf < 2; mf++) {
                    MMA_BF16(s[mf][2*ng],   qfh[kc][mf], bl[0], bl[1]);
                    MMA_BF16(s[mf][2*ng+1], qfh[kc][mf], bl[2], bl[3]);
                }
                #pragma unroll
                for (int mf = 0; mf < 2; mf++) {
                    MMA_BF16(s[mf][2*ng],   qfl[kc][mf], bh[0], bh[1]);
                    MMA_BF16(s[mf][2*ng+1], qfl[kc][mf], bh[2], bh[3]);
                }
            }
        }

        const bool maskw = (k0 + 63) > (q0 + wrow);
        #pragma unroll
        for (int mf = 0; mf < 2; mf++)
            #pragma unroll
            for (int nf = 0; nf < 8; nf++)
                #pragma unroll
                for (int r = 0; r < 4; r++) {
                    float v = s[mf][nf][r] * ASCALE;
                    if (maskw) {
                        int qi = q0 + wrow + mf * 16 + g + ((r >= 2) ? 8 : 0);
                        int kj = k0 + nf * 8 + tig * 2 + (r & 1);
                        if (kj > qi) v += AMASK;
                    }
                    s[mf][nf][r] = v;
                }

        float alpha[2][2];
        #pragma unroll
        for (int mf = 0; mf < 2; mf++)
            #pragma unroll
            for (int h2 = 0; h2 < 2; h2++) {
                float mx = -1e30f;
                #pragma unroll
                for (int nf = 0; nf < 8; nf++)
                    mx = fmaxf(mx, fmaxf(s[mf][nf][h2*2], s[mf][nf][h2*2+1]));
                mx = fmaxf(mx, __shfl_xor_sync(0xffffffffu, mx, 1));
                mx = fmaxf(mx, __shfl_xor_sync(0xffffffffu, mx, 2));
                float mn = fmaxf(m_run[mf][h2], mx);
                float sum = 0.f;
                #pragma unroll
                for (int nf = 0; nf < 8; nf++) {
                    float p0 = exp2f(s[mf][nf][h2*2]   - mn);
                    float p1 = exp2f(s[mf][nf][h2*2+1] - mn);
                    s[mf][nf][h2*2]   = p0;
                    s[mf][nf][h2*2+1] = p1;
                    sum += p0 + p1;
                }
                sum += __shfl_xor_sync(0xffffffffu, sum, 1);
                sum += __shfl_xor_sync(0xffffffffu, sum, 2);
                float a = exp2f(m_run[mf][h2] - mn);
                alpha[mf][h2] = a;
                m_run[mf][h2] = mn;
                l_run[mf][h2] = l_run[mf][h2] * a + sum;
            }

        #pragma unroll
        for (int mf = 0; mf < 2; mf++)
            #pragma unroll
            for (int nf = 0; nf < 8; nf++) {
                o[mf][nf][0] *= alpha[mf][0];
                o[mf][nf][1] *= alpha[mf][0];
                o[mf][nf][2] *= alpha[mf][1];
                o[mf][nf][3] *= alpha[mf][1];
            }

        // ---- O += P V (bf16x3, pass-major) ----
        #pragma unroll
        for (int kc = 0; kc < 4; kc++) {
            uint32_t ph[2][4], pl[2][4];
            #pragma unroll
            for (int mf = 0; mf < 2; mf++) {
                pack_hl(s[mf][2*kc][0],   s[mf][2*kc][1],   ph[mf][0], pl[mf][0]);
                pack_hl(s[mf][2*kc][2],   s[mf][2*kc][3],   ph[mf][1], pl[mf][1]);
                pack_hl(s[mf][2*kc+1][0], s[mf][2*kc+1][1], ph[mf][2], pl[mf][2]);
                pack_hl(s[mf][2*kc+1][2], s[mf][2*kc+1][3], ph[mf][3], pl[mf][3]);
            }
            #pragma unroll
            for (int ng = 0; ng < 4; ng++) {
                uint32_t rv = (uint32_t)(kc * 16 + ((lane >> 3) & 1) * 8 + (lane & 7)) * 144
                              + ng * 32 + (lane >> 4) * 16;
                uint32_t vh[4], vl[4];
                LDMX4T(vh, sVh + rv);
                LDMX4T(vl, sVl + rv);
                #pragma unroll
                for (int mf = 0; mf < 2; mf++) {
                    MMA_BF16(o[mf][2*ng],   ph[mf], vh[0], vh[1]);
                    MMA_BF16(o[mf][2*ng+1], ph[mf], vh[2], vh[3]);
                }
                #pragma unroll
                for (int mf = 0; mf < 2; mf++) {
                    MMA_BF16(o[mf][2*ng],   ph[mf], vl[0], vl[1]);
                    MMA_BF16(o[mf][2*ng+1], ph[mf], vl[2], vl[3]);
                }
                #pragma unroll
                for (int mf = 0; mf < 2; mf++) {
                    MMA_BF16(o[mf][2*ng],   pl[mf], vh[0], vh[1]);
                    MMA_BF16(o[mf][2*ng+1], pl[mf], vh[2], vh[3]);
                }
            }
        }

        if (kt < ktmax) { CP_WAITN(0); __syncthreads(); }
    }

    float inv[2][2];
    #pragma unroll
    for (int mf = 0; mf < 2; mf++) {
        inv[mf][0] = 1.f / l_run[mf][0];
        inv[mf][1] = 1.f / l_run[mf][1];
    }
    #pragma unroll
    for (int mf = 0; mf < 2; mf++) {
        const int r0 = q0 + wrow + mf * 16 + g;
        const size_t m1 = (size_t)b * 2048 + r0;
        const size_t m2 = m1 + 8;
        #pragma unroll
        for (int nf = 0; nf < 8; nf++) {
            const int col = h * 64 + nf * 8 + tig * 2;
            uint32_t h0, l0, h1, l1;
            pack_hl(o[mf][nf][0] * inv[mf][0], o[mf][nf][1] * inv[mf][0], h0, l0);
            pack_hl(o[mf][nf][2] * inv[mf][1], o[mf][nf][3] * inv[mf][1], h1, l1);
            *(uint32_t*)(Ohg + m1 * 1024 + col) = h0;
            *(uint32_t*)(Olg + m1 * 1024 + col) = l0;
            *(uint32_t*)(Ohg + m2 * 1024 + col) = h1;
            *(uint32_t*)(Olg + m2 * 1024 + col) = l1;
        }
    }
    #undef KV_ISSUE
}

// ---------------------------------------------------------------------------
extern "C" void kernel_launch(void* const* d_in, const int* in_sizes, int n_in,
                              void* d_out, int out_size)
{
    const float* q  = (const float*)d_in[0];
    const float* k  = (const float*)d_in[1];
    const float* v  = (const float*)d_in[2];
    const float* Wq = (const float*)d_in[4];
    const float* bq = (const float*)d_in[5];
    const float* Wk = (const float*)d_in[6];
    const float* bk = (const float*)d_in[7];
    const float* Wv = (const float*)d_in[8];
    const float* bv = (const float*)d_in[9];
    const float* Wo = (const float*)d_in[10];
    const float* bo = (const float*)d_in[11];

    float* out = (float*)d_out;                       // [B,S,D]
    float* present = out + (size_t)B_ * S_ * D_;      // [B,2,H,S,DH]

    __nv_bfloat16 *xh0, *xl0, *xh1, *xl1, *xh2, *xl2;
    __nv_bfloat16 *wh0, *wl0, *wh1, *wl1, *wh2, *wl2, *wh3, *wl3;
    __nv_bfloat16 *qbh, *qbl, *kbh, *kbl, *vbh, *vbl;
    cudaGetSymbolAddress((void**)&xh0, g_xh);
    cudaGetSymbolAddress((void**)&xl0, g_xl);
    cudaGetSymbolAddress((void**)&wh0, g_wh);
    cudaGetSymbolAddress((void**)&wl0, g_wl);
    cudaGetSymbolAddress((void**)&qbh, g_qbh);
    cudaGetSymbolAddress((void**)&qbl, g_qbl);
    cudaGetSymbolAddress((void**)&kbh, g_kbh);
    cudaGetSymbolAddress((void**)&kbl, g_kbl);
    cudaGetSymbolAddress((void**)&vbh, g_vbh);
    cudaGetSymbolAddress((void**)&vbl, g_vbl);
    const size_t XSZ = (size_t)4096 * 1024, WSZ = (size_t)1024 * 1024;
    xh1 = xh0 + XSZ; xh2 = xh0 + 2 * XSZ;
    xl1 = xl0 + XSZ; xl2 = xl0 + 2 * XSZ;
    wh1 = wh0 + WSZ; wh2 = wh0 + 2 * WSZ; wh3 = wh0 + 3 * WSZ;
    wl1 = wl0 + WSZ; wl2 = wl0 + 2 * WSZ; wl3 = wl0 + 3 * WSZ;

    const long sB_head = (long)H_ * S_ * DH_;
    const long sH_head = (long)S_ * DH_;

    cudaFuncSetAttribute(gemm_mma_kernel, cudaFuncAttributeMaxDynamicSharedMemorySize, GEMM_SMEM);
    cudaFuncSetAttribute(attn_mma_kernel, cudaFuncAttributeMaxDynamicSharedMemorySize, ATT_SMEM);

    // fused prep
    PrepArgs pa = {q, k, v, Wq, Wk, Wv, Wo, xh0, xl0, xh1, xl1, xh2, xl2};
    prep_kernel<<<16384, 256>>>(pa);

    // fused Q/K/V projections (R10 config)
    GB3 P;
    P.g[0] = {xh0, xl0, wh0, wl0, bq, nullptr, 0, 0, 0, qbh, qbl};
    P.g[1] = {xh1, xl1, wh1, wl1, bk, present, 2 * sB_head, (long)DH_, sH_head, kbh, kbl};
    P.g[2] = {xh2, xl2, wh2, wl2, bv, present + (size_t)sB_head,
              2 * sB_head, (long)DH_, sH_head, vbh, vbl};
    gemm_mma_kernel<<<dim3(8, 32, 3), 256, GEMM_SMEM>>>(P);

    // attention: ctx written as bf16 hi/lo into g_xh[0]/g_xl[0]
    attn_mma_kernel<<<(S_ / 128) * H_ * B_, 128, ATT_SMEM>>>(
        qbh, qbl, kbh, kbl, vbh, vbl, xh0, xl0);

    // output projection: out = ctx @ Wo + bo
    GB3 PO;
    PO.g[0] = {xh0, xl0, wh3, wl3, bo, out, (long)S_ * D_, (long)D_, (long)DH_,
               nullptr, nullptr};
    PO.g[1] = PO.g[0];
    PO.g[2] = PO.g[0];
    gemm_mma_kernel<<<dim3(8, 32, 1), 256, GEMM_SMEM>>>(PO);
}

// round 14
// speedup vs baseline: 1.3890x; 1.3459x over previous
#include <cuda_runtime.h>
#include <cuda_fp16.h>
#include <cstdint>

#define B_  2
#define S_  2048
#define D_  1024
#define H_  16
#define DH_ 64

// ---------------------------------------------------------------------------
// Scratch (device globals — no allocation allowed)
// ---------------------------------------------------------------------------
__device__ __half g_xh[3][(size_t)4096 * 1024];  // fp16 of X (q,k,v); [0] reused for ctx
__device__ __half g_wh[4][(size_t)1024 * 1024];  // fp16-hi of W^T (q,k,v,o)
__device__ __half g_wl[4][(size_t)1024 * 1024];  // fp16-lo
__device__ __half g_qbh[(size_t)B_ * H_ * S_ * DH_];  // Q fp16 [B,H,S,DH]
__device__ __half g_kbh[(size_t)B_ * H_ * S_ * DH_];  // K fp16 hi
__device__ __half g_kbl[(size_t)B_ * H_ * S_ * DH_];  // K fp16 lo
__device__ __half g_vbh[(size_t)B_ * H_ * S_ * DH_];  // V fp16 hi
__device__ __half g_vbl[(size_t)B_ * H_ * S_ * DH_];  // V fp16 lo

// ---------------------------------------------------------------------------
__device__ __forceinline__ uint32_t smem_u32(const void* p) {
    uint32_t a;
    asm("{ .reg .u64 t; cvta.to.shared.u64 t, %1; cvt.u32.u64 %0, t; }" : "=r"(a) : "l"(p));
    return a;
}

#define LDMX4(r, addr) \
    asm volatile("ldmatrix.sync.aligned.m8n8.x4.shared.b16 {%0,%1,%2,%3}, [%4];" \
        : "=r"((r)[0]), "=r"((r)[1]), "=r"((r)[2]), "=r"((r)[3]) : "r"(addr))

#define LDMX4T(r, addr) \
    asm volatile("ldmatrix.sync.aligned.m8n8.x4.trans.shared.b16 {%0,%1,%2,%3}, [%4];" \
        : "=r"((r)[0]), "=r"((r)[1]), "=r"((r)[2]), "=r"((r)[3]) : "r"(addr))

#define MMA_F16(d, a, b0, b1) \
    asm volatile("mma.sync.aligned.m16n8k16.row.col.f32.f16.f16.f32 " \
        "{%0,%1,%2,%3}, {%4,%5,%6,%7}, {%8,%9}, {%0,%1,%2,%3};" \
        : "+f"((d)[0]), "+f"((d)[1]), "+f"((d)[2]), "+f"((d)[3]) \
        : "r"((a)[0]), "r"((a)[1]), "r"((a)[2]), "r"((a)[3]), "r"(b0), "r"(b1))

#define CP_ASYNC16(sa, gp) \
    asm volatile("cp.async.cg.shared.global [%0], [%1], 16;" :: "r"(sa), "l"(gp))
#define CP_COMMIT() asm volatile("cp.async.commit_group;" ::: "memory")
#define CP_WAITN(n) asm volatile("cp.async.wait_group %0;" :: "n"(n) : "memory")

__device__ __forceinline__ uint32_t pack_h(float v0, float v1) {
    __half2 h2 = __floats2half2_rn(v0, v1);
    return *reinterpret_cast<uint32_t*>(&h2);
}
__device__ __forceinline__ void pack_hl(float v0, float v1, uint32_t& hi, uint32_t& lo) {
    __half2 h2 = __floats2half2_rn(v0, v1);
    float2 f = __half22float2(h2);
    __half2 l2 = __floats2half2_rn(v0 - f.x, v1 - f.y);
    hi = *reinterpret_cast<uint32_t*>(&h2);
    lo = *reinterpret_cast<uint32_t*>(&l2);
}

// ---------------------------------------------------------------------------
// Fused prep: blocks [0,12288) = fp16 casts of q,k,v;
//             blocks [12288,16384) = transpose + fp16 hi/lo split of weights.
// ---------------------------------------------------------------------------
struct PrepArgs {
    const float *q, *k, *v, *W0, *W1, *W2, *W3;
    __half *xh0, *xh1, *xh2;
};

__global__ __launch_bounds__(256) void prep_kernel(PrepArgs a)
{
    __shared__ float ts[32][33];
    const int bid = blockIdx.x;
    if (bid < 12288) {
        const int z = bid >> 12;
        const int blk = bid & 4095;
        const float* x = (z == 0) ? a.q : (z == 1) ? a.k : a.v;
        __half* hi = (z == 0) ? a.xh0 : (z == 1) ? a.xh1 : a.xh2;
        int i = blk * 256 + threadIdx.x;
        float4 v4 = ((const float4*)x)[i];
        ((uint32_t*)hi)[i * 2]     = pack_h(v4.x, v4.y);
        ((uint32_t*)hi)[i * 2 + 1] = pack_h(v4.z, v4.w);
    } else {
        const int j = bid - 12288;
        const int z = j >> 10;
        const int r = j & 1023;
        const int kb = (r >> 5) << 5, nb = (r & 31) << 5;
        const float* W = (z == 0) ? a.W0 : (z == 1) ? a.W1 : (z == 2) ? a.W2 : a.W3;
        __half* th = g_wh[z];
        __half* tl = g_wl[z];
        int tx = threadIdx.x & 31, ty = threadIdx.x >> 5;
        #pragma unroll
        for (int jj = 0; jj < 4; jj++)
            ts[ty + jj * 8][tx] = W[(size_t)(kb + ty + jj * 8) * 1024 + nb + tx];
        __syncthreads();
        #pragma unroll
        for (int jj = 0; jj < 4; jj++) {
            int n = nb + ty + jj * 8, kk = kb + tx;
            float v = ts[tx][ty + jj * 8];
            __half h = __float2half_rn(v);
            th[(size_t)n * 1024 + kk] = h;
            tl[(size_t)n * 1024 + kk] = __float2half_rn(v - __half2float(h));
        }
    }
}

// ---------------------------------------------------------------------------
// fp16x2 mma.sync GEMM: out = X @ W + bias, D = Ah*Bh + Ah*Bl.
// A single fp16 [M,K]; B = W^T fp16 hi/lo [N,K]. CTA 128x128, K-tile 32,
// 2-stage, 8 warps (64x32), single sync per k-tile. 3 smem mats/stage.
// ---------------------------------------------------------------------------
struct GB {
    const __half *Ah, *Bh, *Bl;
    const float* bias;
    float* out; long sB, sS, sH;
    __half *oh, *ol;
};
struct GB3 { GB g[3]; };

#define SA_STRIDE 80
#define MAT_BYTES (128 * SA_STRIDE)
#define STG_BYTES (3 * MAT_BYTES)           // Ah|Bh|Bl = 30720
#define GEMM_SMEM (2 * STG_BYTES)           // 61440

__global__ __launch_bounds__(256) void gemm_mma_kernel(GB3 P)
{
    const GB p = P.g[blockIdx.z];
    extern __shared__ char sm[];
    const uint32_t sbase = smem_u32(sm);
    const int tid = threadIdx.x, lane = tid & 31, wid = tid >> 5;
    const int wm = wid & 1, wn = wid >> 1;
    const int m0 = blockIdx.y * 128, n0 = blockIdx.x * 128;

    float acc[4][4][4] = {};

    const int arow  = lane & 15;
    const int akoff = (lane >> 4) * 16;
    const int brow  = ((lane >> 4) << 3) | (lane & 7);
    const int bkoff = ((lane >> 3) & 1) * 16;

    // per stage: 3 mats x 128 rows x 4 chunks of 16B = 1536 chunks; 6/thread
    #define ISSUE(t) do { \
        const int k0i = (t) * 32; \
        const uint32_t sdst = sbase + ((t) & 1) * STG_BYTES; \
        _Pragma("unroll") \
        for (int i = 0; i < 6; i++) { \
            int idx = tid + i * 256; \
            int mat = idx >> 9, chunk = idx & 511; \
            int row = chunk >> 2, c = chunk & 3; \
            const __half* gp; \
            if (mat == 0)      gp = p.Ah + (size_t)(m0 + row) * 1024 + k0i + c * 8; \
            else if (mat == 1) gp = p.Bh + (size_t)(n0 + row) * 1024 + k0i + c * 8; \
            else               gp = p.Bl + (size_t)(n0 + row) * 1024 + k0i + c * 8; \
            uint32_t sa = sdst + mat * MAT_BYTES + row * SA_STRIDE + c * 16; \
            CP_ASYNC16(sa, gp); \
        } \
        CP_COMMIT(); \
    } while (0)

    ISSUE(0);
    CP_WAITN(0);
    __syncthreads();

    for (int t = 0; t < 32; t++) {
        if (t < 31) ISSUE(t + 1);

        const uint32_t s0  = sbase + (t & 1) * STG_BYTES;
        const uint32_t pAh = s0;
        const uint32_t pBh = s0 + MAT_BYTES;
        const uint32_t pBl = s0 + 2 * MAT_BYTES;

        #pragma unroll
        for (int ks = 0; ks < 2; ks++) {
            uint32_t ah[4][4];
            #pragma unroll
            for (int mf = 0; mf < 4; mf++) {
                uint32_t ra = (uint32_t)(wm * 64 + mf * 16 + arow) * SA_STRIDE + ks * 32 + akoff;
                LDMX4(ah[mf], pAh + ra);
            }
            uint32_t bh[2][4], bl[2][4];
            #pragma unroll
            for (int ng = 0; ng < 2; ng++) {
                uint32_t rb = (uint32_t)(wn * 32 + ng * 16 + brow) * SA_STRIDE + ks * 32 + bkoff;
                LDMX4(bh[ng], pBh + rb);
                LDMX4(bl[ng], pBl + rb);
            }
            #pragma unroll
            for (int mf = 0; mf < 4; mf++)
                #pragma unroll
                for (int nf = 0; nf < 4; nf++) {
                    const uint32_t* bhp = &bh[nf >> 1][(nf & 1) * 2];
                    MMA_F16(acc[mf][nf], ah[mf], bhp[0], bhp[1]);
                }
            #pragma unroll
            for (int mf = 0; mf < 4; mf++)
                #pragma unroll
                for (int nf = 0; nf < 4; nf++) {
                    const uint32_t* blp = &bl[nf >> 1][(nf & 1) * 2];
                    MMA_F16(acc[mf][nf], ah[mf], blp[0], blp[1]);
                }
        }

        if (t < 31) { CP_WAITN(0); __syncthreads(); }
    }

    // ---- epilogue ----
    const int g = lane >> 2, tig = lane & 3;
    const long s2S = DH_, s2H = (long)S_ * DH_, s2B = (long)H_ * S_ * DH_;
    #pragma unroll
    for (int mf = 0; mf < 4; mf++) {
        const int mA = m0 + wm * 64 + mf * 16 + g;
        const int b1 = mA >> 11, s1 = mA & 2047;
        const int b2 = (mA + 8) >> 11, s2 = (mA + 8) & 2047;
        #pragma unroll
        for (int nf = 0; nf < 4; nf++) {
            const int n = n0 + wn * 32 + nf * 8 + tig * 2;
            const int h = n >> 6, d = n & 63;
            const float bv0 = __ldg(p.bias + n), bv1 = __ldg(p.bias + n + 1);
            float p0 = acc[mf][nf][0] + bv0, p1 = acc[mf][nf][1] + bv1;
            float p2 = acc[mf][nf][2] + bv0, p3 = acc[mf][nf][3] + bv1;
            if (p.out) {
                float2 lo_pair, hi_pair;
                lo_pair.x = p0; lo_pair.y = p1;
                hi_pair.x = p2; hi_pair.y = p3;
                *(float2*)(p.out + (size_t)b1 * p.sB + (size_t)s1 * p.sS + (size_t)h * p.sH + d) = lo_pair;
                *(float2*)(p.out + (size_t)b2 * p.sB + (size_t)s2 * p.sS + (size_t)h * p.sH + d) = hi_pair;
            }
            if (p.oh) {
                size_t i1 = (size_t)b1 * s2B + (size_t)s1 * s2S + (size_t)h * s2H + d;
                size_t i2 = (size_t)b2 * s2B + (size_t)s2 * s2S + (size_t)h * s2H + d;
                if (p.ol) {
                    uint32_t h0, l0, h1, l1;
                    pack_hl(p0, p1, h0, l0);
                    pack_hl(p2, p3, h1, l1);
                    *(uint32_t*)(p.oh + i1) = h0;
                    *(uint32_t*)(p.ol + i1) = l0;
                    *(uint32_t*)(p.oh + i2) = h1;
                    *(uint32_t*)(p.ol + i2) = l1;
                } else {
                    *(uint32_t*)(p.oh + i1) = pack_h(p0, p1);
                    *(uint32_t*)(p.oh + i2) = pack_h(p2, p3);
                }
            }
        }
    }
    #undef ISSUE
}

// ---------------------------------------------------------------------------
// Tensor-core flash attention (fp16x2, causal, exp2 softmax).
// Q single fp16; K,V fp16 hi/lo. S = Qh*Kh + Qh*Kl; O += Ph*Vh + Ph*Vl.
// 128 q/CTA, 4 warps, KV double-buffered, single sync per k-tile.
// ---------------------------------------------------------------------------
#define LOG2E      1.4426950408889634f
#define ASCALE     (0.125f * LOG2E)
#define AMASK      (-10000.0f * LOG2E)

#define QT_BYTES   (128 * 144)
#define KVMAT      (64 * 144)
#define KVSTG      (4 * KVMAT)
#define ATT_SMEM   (QT_BYTES + 2 * KVSTG)   // 92160

__global__ __launch_bounds__(128) void attn_mma_kernel(
    const __half* __restrict__ Qhg,
    const __half* __restrict__ Khg, const __half* __restrict__ Klg,
    const __half* __restrict__ Vhg, const __half* __restrict__ Vlg,
    __half* __restrict__ Ohg)
{
    extern __shared__ char sm[];
    const uint32_t sb  = smem_u32(sm);
    const uint32_t sQh = sb;
    const uint32_t sKV = sb + QT_BYTES;

    const int tid = threadIdx.x, lane = tid & 31, wid = tid >> 5;
    const int bidx = blockIdx.x;
    const int qblk = (S_ / 128 - 1) - (bidx >> 5);
    const int hb = bidx & 31;
    const int h = hb & 15, b = hb >> 4;
    const int q0 = qblk * 128;
    const int wrow = wid * 32;
    const int g = lane >> 2, tig = lane & 3;

    const size_t hoff = ((size_t)(b * H_ + h) * S_) * DH_;
    const __half* qh_p = Qhg + hoff + (size_t)q0 * DH_;
    const __half* kh_p = Khg + hoff;
    const __half* kl_p = Klg + hoff;
    const __half* vh_p = Vhg + hoff;
    const __half* vl_p = Vlg + hoff;

    #define KV_ISSUE(k0v, st) do { \
        const uint32_t sst = sKV + (st) * KVSTG; \
        _Pragma("unroll") \
        for (int i = 0; i < 16; i++) { \
            int idx = tid + i * 128; \
            int mat = idx >> 9, rem = idx & 511, row = rem >> 3, c = rem & 7; \
            const __half* gp; uint32_t sa; \
            if (mat == 0)      { gp = kh_p; sa = sst; } \
            else if (mat == 1) { gp = kl_p; sa = sst + KVMAT; } \
            else if (mat == 2) { gp = vh_p; sa = sst + 2 * KVMAT; } \
            else               { gp = vl_p; sa = sst + 3 * KVMAT; } \
            gp += (size_t)((k0v) + row) * 64 + c * 8; \
            sa += row * 144 + c * 16; \
            CP_ASYNC16(sa, gp); \
        } \
        CP_COMMIT(); \
    } while (0)

    const int ktmax = 2 * qblk + 1;

    // ---- prologue: Q (1024 chunks) + KV0 in one commit group ----
    #pragma unroll
    for (int i = 0; i < 8; i++) {
        int idx = tid + i * 128;
        int row = idx >> 3, c = idx & 7;
        CP_ASYNC16(sQh + row * 144 + c * 16, qh_p + row * 64 + c * 8);
    }
    KV_ISSUE(0, 0);
    CP_WAITN(0);
    __syncthreads();

    // ---- hoist Q fragments ----
    uint32_t qf[4][2][4];
    #pragma unroll
    for (int kc = 0; kc < 4; kc++)
        #pragma unroll
        for (int mf = 0; mf < 2; mf++) {
            uint32_t ra = (uint32_t)(wrow + mf * 16 + (lane & 15)) * 144
                          + kc * 32 + (lane >> 4) * 16;
            LDMX4(qf[kc][mf], sQh + ra);
        }

    float o[2][8][4] = {};
    float m_run[2][2] = {{-1e30f, -1e30f}, {-1e30f, -1e30f}};
    float l_run[2][2] = {};

    for (int kt = 0; kt <= ktmax; kt++) {
        const int k0 = kt * 64;
        const uint32_t sst = sKV + (kt & 1) * KVSTG;
        const uint32_t sKh = sst, sKl = sst + KVMAT;
        const uint32_t sVh = sst + 2 * KVMAT, sVl = sst + 3 * KVMAT;

        if (kt < ktmax) KV_ISSUE(k0 + 64, (kt + 1) & 1);

        // ---- S = Q K^T (fp16x2) ----
        float s[2][8][4] = {};
        #pragma unroll
        for (int kc = 0; kc < 4; kc++) {
            #pragma unroll
            for (int ng = 0; ng < 4; ng++) {
                uint32_t rb = (uint32_t)(ng * 16 + ((lane >> 4) << 3) + (lane & 7)) * 144
                              + kc * 32 + ((lane >> 3) & 1) * 16;
                uint32_t kh[4], kl[4];
                LDMX4(kh, sKh + rb);
                LDMX4(kl, sKl + rb);
                #pragma unroll
                for (int mf = 0; mf < 2; mf++) {
                    MMA_F16(s[mf][2*ng],   qf[kc][mf], kh[0], kh[1]);
                    MMA_F16(s[mf][2*ng+1], qf[kc][mf], kh[2], kh[3]);
                }
                #pragma unroll
                for (int mf = 0; mf < 2; mf++) {
                    MMA_F16(s[mf][2*ng],   qf[kc][mf], kl[0], kl[1]);
                    MMA_F16(s[mf][2*ng+1], qf[kc][mf], kl[2], kl[3]);
                }
            }
        }

        // ---- scale + causal mask (log2 domain) ----
        const bool maskw = (k0 + 63) > (q0 + wrow);
        #pragma unroll
        for (int mf = 0; mf < 2; mf++)
            #pragma unroll
            for (int nf = 0; nf < 8; nf++)
                #pragma unroll
                for (int r = 0; r < 4; r++) {
                    float v = s[mf][nf][r] * ASCALE;
                    if (maskw) {
                        int qi = q0 + wrow + mf * 16 + g + ((r >= 2) ? 8 : 0);
                        int kj = k0 + nf * 8 + tig * 2 + (r & 1);
                        if (kj > qi) v += AMASK;
                    }
                    s[mf][nf][r] = v;
                }

        // ---- online softmax (exp2) ----
        float alpha[2][2];
        #pragma unroll
        for (int mf = 0; mf < 2; mf++)
            #pragma unroll
            for (int h2 = 0; h2 < 2; h2++) {
                float mx = -1e30f;
                #pragma unroll
                for (int nf = 0; nf < 8; nf++)
                    mx = fmaxf(mx, fmaxf(s[mf][nf][h2*2], s[mf][nf][h2*2+1]));
                mx = fmaxf(mx, __shfl_xor_sync(0xffffffffu, mx, 1));
                mx = fmaxf(mx, __shfl_xor_sync(0xffffffffu, mx, 2));
                float mn = fmaxf(m_run[mf][h2], mx);
                float sum = 0.f;
                #pragma unroll
                for (int nf = 0; nf < 8; nf++) {
                    float p0 = exp2f(s[mf][nf][h2*2]   - mn);
                    float p1 = exp2f(s[mf][nf][h2*2+1] - mn);
                    s[mf][nf][h2*2]   = p0;
                    s[mf][nf][h2*2+1] = p1;
                    sum += p0 + p1;
                }
                sum += __shfl_xor_sync(0xffffffffu, sum, 1);
                sum += __shfl_xor_sync(0xffffffffu, sum, 2);
                float a = exp2f(m_run[mf][h2] - mn);
                alpha[mf][h2] = a;
                m_run[mf][h2] = mn;
                l_run[mf][h2] = l_run[mf][h2] * a + sum;
            }

        #pragma unroll
        for (int mf = 0; mf < 2; mf++)
            #pragma unroll
            for (int nf = 0; nf < 8; nf++) {
                o[mf][nf][0] *= alpha[mf][0];
                o[mf][nf][1] *= alpha[mf][0];
                o[mf][nf][2] *= alpha[mf][1];
                o[mf][nf][3] *= alpha[mf][1];
            }

        // ---- O += P V (fp16x2) ----
        #pragma unroll
        for (int kc = 0; kc < 4; kc++) {
            uint32_t ph[2][4];
            #pragma unroll
            for (int mf = 0; mf < 2; mf++) {
                ph[mf][0] = pack_h(s[mf][2*kc][0],   s[mf][2*kc][1]);
                ph[mf][1] = pack_h(s[mf][2*kc][2],   s[mf][2*kc][3]);
                ph[mf][2] = pack_h(s[mf][2*kc+1][0], s[mf][2*kc+1][1]);
                ph[mf][3] = pack_h(s[mf][2*kc+1][2], s[mf][2*kc+1][3]);
            }
            #pragma unroll
            for (int ng = 0; ng < 4; ng++) {
                uint32_t rv = (uint32_t)(kc * 16 + ((lane >> 3) & 1) * 8 + (lane & 7)) * 144
                              + ng * 32 + (lane >> 4) * 16;
                uint32_t vh[4], vl[4];
                LDMX4T(vh, sVh + rv);
                LDMX4T(vl, sVl + rv);
                #pragma unroll
                for (int mf = 0; mf < 2; mf++) {
                    MMA_F16(o[mf][2*ng],   ph[mf], vh[0], vh[1]);
                    MMA_F16(o[mf][2*ng+1], ph[mf], vh[2], vh[3]);
                }
                #pragma unroll
                for (int mf = 0; mf < 2; mf++) {
                    MMA_F16(o[mf][2*ng],   ph[mf], vl[0], vl[1]);
                    MMA_F16(o[mf][2*ng+1], ph[mf], vl[2], vl[3]);
                }
            }
        }

        if (kt < ktmax) { CP_WAITN(0); __syncthreads(); }
    }

    // ---- epilogue: ctx -> fp16 into GEMM A buffer ----
    float inv[2][2];
    #pragma unroll
    for (int mf = 0; mf < 2; mf++) {
        inv[mf][0] = 1.f / l_run[mf][0];
        inv[mf][1] = 1.f / l_run[mf][1];
    }
    #pragma unroll
    for (int mf = 0; mf < 2; mf++) {
        const int r0 = q0 + wrow + mf * 16 + g;
        const size_t m1 = (size_t)b * 2048 + r0;
        const size_t m2 = m1 + 8;
        #pragma unroll
        for (int nf = 0; nf < 8; nf++) {
            const int col = h * 64 + nf * 8 + tig * 2;
            *(uint32_t*)(Ohg + m1 * 1024 + col) =
                pack_h(o[mf][nf][0] * inv[mf][0], o[mf][nf][1] * inv[mf][0]);
            *(uint32_t*)(Ohg + m2 * 1024 + col) =
                pack_h(o[mf][nf][2] * inv[mf][1], o[mf][nf][3] * inv[mf][1]);
        }
    }
    #undef KV_ISSUE
}

// ---------------------------------------------------------------------------
extern "C" void kernel_launch(void* const* d_in, const int* in_sizes, int n_in,
                              void* d_out, int out_size)
{
    const float* q  = (const float*)d_in[0];
    const float* k  = (const float*)d_in[1];
    const float* v  = (const float*)d_in[2];
    const float* Wq = (const float*)d_in[4];
    const float* bq = (const float*)d_in[5];
    const float* Wk = (const float*)d_in[6];
    const float* bk = (const float*)d_in[7];
    const float* Wv = (const float*)d_in[8];
    const float* bv = (const float*)d_in[9];
    const float* Wo = (const float*)d_in[10];
    const float* bo = (const float*)d_in[11];

    float* out = (float*)d_out;                       // [B,S,D]
    float* present = out + (size_t)B_ * S_ * D_;      // [B,2,H,S,DH]

    __half *xh0, *xh1, *xh2;
    __half *wh0, *wl0, *wh1, *wl1, *wh2, *wl2, *wh3, *wl3;
    __half *qbh, *kbh, *kbl, *vbh, *vbl;
    cudaGetSymbolAddress((void**)&xh0, g_xh);
    cudaGetSymbolAddress((void**)&wh0, g_wh);
    cudaGetSymbolAddress((void**)&wl0, g_wl);
    cudaGetSymbolAddress((void**)&qbh, g_qbh);
    cudaGetSymbolAddress((void**)&kbh, g_kbh);
    cudaGetSymbolAddress((void**)&kbl, g_kbl);
    cudaGetSymbolAddress((void**)&vbh, g_vbh);
    cudaGetSymbolAddress((void**)&vbl, g_vbl);
    const size_t XSZ = (size_t)4096 * 1024, WSZ = (size_t)1024 * 1024;
    xh1 = xh0 + XSZ; xh2 = xh0 + 2 * XSZ;
    wh1 = wh0 + WSZ; wh2 = wh0 + 2 * WSZ; wh3 = wh0 + 3 * WSZ;
    wl1 = wl0 + WSZ; wl2 = wl0 + 2 * WSZ; wl3 = wl0 + 3 * WSZ;

    const long sB_head = (long)H_ * S_ * DH_;
    const long sH_head = (long)S_ * DH_;

    cudaFuncSetAttribute(gemm_mma_kernel, cudaFuncAttributeMaxDynamicSharedMemorySize, GEMM_SMEM);
    cudaFuncSetAttribute(attn_mma_kernel, cudaFuncAttributeMaxDynamicSharedMemorySize, ATT_SMEM);

    // fused prep
    PrepArgs pa = {q, k, v, Wq, Wk, Wv, Wo, xh0, xh1, xh2};
    prep_kernel<<<16384, 256>>>(pa);

    // fused Q/K/V projections
    GB3 P;
    P.g[0] = {xh0, wh0, wl0, bq, nullptr, 0, 0, 0, qbh, nullptr};
    P.g[1] = {xh1, wh1, wl1, bk, present, 2 * sB_head, (long)DH_, sH_head, kbh, kbl};
    P.g[2] = {xh2, wh2, wl2, bv, present + (size_t)sB_head,
              2 * sB_head, (long)DH_, sH_head, vbh, vbl};
    gemm_mma_kernel<<<dim3(8, 32, 3), 256, GEMM_SMEM>>>(P);

    // attention: ctx written as fp16 into g_xh[0]
    attn_mma_kernel<<<(S_ / 128) * H_ * B_, 128, ATT_SMEM>>>(
        qbh, kbh, kbl, vbh, vbl, xh0);

    // output projection: out = ctx @ Wo + bo
    GB3 PO;
    PO.g[0] = {xh0, wh3, wl3, bo, out, (long)S_ * D_, (long)D_, (long)DH_,
               nullptr, nullptr};
    PO.g[1] = PO.g[0];
    PO.g[2] = PO.g[0];
    gemm_mma_kernel<<<dim3(8, 32, 1), 256, GEMM_SMEM>>>(PO);
}

// round 15
// speedup vs baseline: 2.4289x; 1.7486x over previous
#include <cuda_runtime.h>
#include <cuda_fp16.h>
#include <cstdint>

#define B_  2
#define S_  2048
#define D_  1024
#define H_  16
#define DH_ 64

// ---------------------------------------------------------------------------
// Scratch (device globals — no allocation allowed)
// ---------------------------------------------------------------------------
__device__ __half g_xh[3][(size_t)4096 * 1024];  // fp16 of X (q,k,v); [0] reused for ctx
__device__ __half g_wh[4][(size_t)1024 * 1024];  // fp16 of W^T (q,k,v,o)
__device__ __half g_qbh[(size_t)B_ * H_ * S_ * DH_];  // Q fp16 [B,H,S,DH]
__device__ __half g_kbh[(size_t)B_ * H_ * S_ * DH_];  // K fp16
__device__ __half g_vbh[(size_t)B_ * H_ * S_ * DH_];  // V fp16

// ---------------------------------------------------------------------------
__device__ __forceinline__ uint32_t smem_u32(const void* p) {
    uint32_t a;
    asm("{ .reg .u64 t; cvta.to.shared.u64 t, %1; cvt.u32.u64 %0, t; }" : "=r"(a) : "l"(p));
    return a;
}

#define LDMX4(r, addr) \
    asm volatile("ldmatrix.sync.aligned.m8n8.x4.shared.b16 {%0,%1,%2,%3}, [%4];" \
        : "=r"((r)[0]), "=r"((r)[1]), "=r"((r)[2]), "=r"((r)[3]) : "r"(addr))

#define LDMX4T(r, addr) \
    asm volatile("ldmatrix.sync.aligned.m8n8.x4.trans.shared.b16 {%0,%1,%2,%3}, [%4];" \
        : "=r"((r)[0]), "=r"((r)[1]), "=r"((r)[2]), "=r"((r)[3]) : "r"(addr))

#define MMA_F16(d, a, b0, b1) \
    asm volatile("mma.sync.aligned.m16n8k16.row.col.f32.f16.f16.f32 " \
        "{%0,%1,%2,%3}, {%4,%5,%6,%7}, {%8,%9}, {%0,%1,%2,%3};" \
        : "+f"((d)[0]), "+f"((d)[1]), "+f"((d)[2]), "+f"((d)[3]) \
        : "r"((a)[0]), "r"((a)[1]), "r"((a)[2]), "r"((a)[3]), "r"(b0), "r"(b1))

#define CP_ASYNC16(sa, gp) \
    asm volatile("cp.async.cg.shared.global [%0], [%1], 16;" :: "r"(sa), "l"(gp))
#define CP_COMMIT() asm volatile("cp.async.commit_group;" ::: "memory")
#define CP_WAITN(n) asm volatile("cp.async.wait_group %0;" :: "n"(n) : "memory")

__device__ __forceinline__ uint32_t pack_h(float v0, float v1) {
    __half2 h2 = __floats2half2_rn(v0, v1);
    return *reinterpret_cast<uint32_t*>(&h2);
}

// ---------------------------------------------------------------------------
// Fused prep: blocks [0,12288) = fp16 casts of q,k,v;
//             blocks [12288,16384) = transpose + fp16 cast of the 4 weights.
// ---------------------------------------------------------------------------
struct PrepArgs {
    const float *q, *k, *v, *W0, *W1, *W2, *W3;
    __half *xh0, *xh1, *xh2;
};

__global__ __launch_bounds__(256) void prep_kernel(PrepArgs a)
{
    __shared__ float ts[32][33];
    const int bid = blockIdx.x;
    if (bid < 12288) {
        const int z = bid >> 12;
        const int blk = bid & 4095;
        const float* x = (z == 0) ? a.q : (z == 1) ? a.k : a.v;
        __half* hi = (z == 0) ? a.xh0 : (z == 1) ? a.xh1 : a.xh2;
        int i = blk * 256 + threadIdx.x;
        float4 v4 = ((const float4*)x)[i];
        ((uint32_t*)hi)[i * 2]     = pack_h(v4.x, v4.y);
        ((uint32_t*)hi)[i * 2 + 1] = pack_h(v4.z, v4.w);
    } else {
        const int j = bid - 12288;
        const int z = j >> 10;
        const int r = j & 1023;
        const int kb = (r >> 5) << 5, nb = (r & 31) << 5;
        const float* W = (z == 0) ? a.W0 : (z == 1) ? a.W1 : (z == 2) ? a.W2 : a.W3;
        __half* th = g_wh[z];
        int tx = threadIdx.x & 31, ty = threadIdx.x >> 5;
        #pragma unroll
        for (int jj = 0; jj < 4; jj++)
            ts[ty + jj * 8][tx] = W[(size_t)(kb + ty + jj * 8) * 1024 + nb + tx];
        __syncthreads();
        #pragma unroll
        for (int jj = 0; jj < 4; jj++) {
            int n = nb + ty + jj * 8, kk = kb + tx;
            th[(size_t)n * 1024 + kk] = __float2half_rn(ts[tx][ty + jj * 8]);
        }
    }
}

// ---------------------------------------------------------------------------
// fp16 mma.sync GEMM: out = X @ W + bias (single pass).
// CTA 128x128, K-tile 32, 2-stage, 8 warps (64x32), single sync per k-tile.
// ---------------------------------------------------------------------------
struct GB {
    const __half *Ah, *Bh;
    const float* bias;
    float* out; long sB, sS, sH;
    __half *oh;
};
struct GB3 { GB g[3]; };

#define SA_STRIDE 80
#define MAT_BYTES (128 * SA_STRIDE)
#define STG_BYTES (2 * MAT_BYTES)           // Ah|Bh = 20480
#define GEMM_SMEM (2 * STG_BYTES)           // 40960

__global__ __launch_bounds__(256) void gemm_mma_kernel(GB3 P)
{
    const GB p = P.g[blockIdx.z];
    extern __shared__ char sm[];
    const uint32_t sbase = smem_u32(sm);
    const int tid = threadIdx.x, lane = tid & 31, wid = tid >> 5;
    const int wm = wid & 1, wn = wid >> 1;
    const int m0 = blockIdx.y * 128, n0 = blockIdx.x * 128;

    float acc[4][4][4] = {};

    const int arow  = lane & 15;
    const int akoff = (lane >> 4) * 16;
    const int brow  = ((lane >> 4) << 3) | (lane & 7);
    const int bkoff = ((lane >> 3) & 1) * 16;

    // per stage: 2 mats x 128 rows x 4 chunks of 16B = 1024 chunks; 4/thread
    #define ISSUE(t) do { \
        const int k0i = (t) * 32; \
        const uint32_t sdst = sbase + ((t) & 1) * STG_BYTES; \
        _Pragma("unroll") \
        for (int i = 0; i < 4; i++) { \
            int idx = tid + i * 256; \
            int mat = idx >> 9, chunk = idx & 511; \
            int row = chunk >> 2, c = chunk & 3; \
            const __half* gp = (mat ? p.Bh + (size_t)(n0 + row) * 1024 \
                                    : p.Ah + (size_t)(m0 + row) * 1024) + k0i + c * 8; \
            uint32_t sa = sdst + mat * MAT_BYTES + row * SA_STRIDE + c * 16; \
            CP_ASYNC16(sa, gp); \
        } \
        CP_COMMIT(); \
    } while (0)

    ISSUE(0);
    CP_WAITN(0);
    __syncthreads();

    for (int t = 0; t < 32; t++) {
        if (t < 31) ISSUE(t + 1);

        const uint32_t s0  = sbase + (t & 1) * STG_BYTES;
        const uint32_t pAh = s0;
        const uint32_t pBh = s0 + MAT_BYTES;

        #pragma unroll
        for (int ks = 0; ks < 2; ks++) {
            uint32_t ah[4][4];
            #pragma unroll
            for (int mf = 0; mf < 4; mf++) {
                uint32_t ra = (uint32_t)(wm * 64 + mf * 16 + arow) * SA_STRIDE + ks * 32 + akoff;
                LDMX4(ah[mf], pAh + ra);
            }
            uint32_t bh[2][4];
            #pragma unroll
            for (int ng = 0; ng < 2; ng++) {
                uint32_t rb = (uint32_t)(wn * 32 + ng * 16 + brow) * SA_STRIDE + ks * 32 + bkoff;
                LDMX4(bh[ng], pBh + rb);
            }
            #pragma unroll
            for (int mf = 0; mf < 4; mf++)
                #pragma unroll
                for (int nf = 0; nf < 4; nf++) {
                    const uint32_t* bhp = &bh[nf >> 1][(nf & 1) * 2];
                    MMA_F16(acc[mf][nf], ah[mf], bhp[0], bhp[1]);
                }
        }

        if (t < 31) { CP_WAITN(0); __syncthreads(); }
    }

    // ---- epilogue ----
    const int g = lane >> 2, tig = lane & 3;
    const long s2S = DH_, s2H = (long)S_ * DH_, s2B = (long)H_ * S_ * DH_;
    #pragma unroll
    for (int mf = 0; mf < 4; mf++) {
        const int mA = m0 + wm * 64 + mf * 16 + g;
        const int b1 = mA >> 11, s1 = mA & 2047;
        const int b2 = (mA + 8) >> 11, s2 = (mA + 8) & 2047;
        #pragma unroll
        for (int nf = 0; nf < 4; nf++) {
            const int n = n0 + wn * 32 + nf * 8 + tig * 2;
            const int h = n >> 6, d = n & 63;
            const float bv0 = __ldg(p.bias + n), bv1 = __ldg(p.bias + n + 1);
            float p0 = acc[mf][nf][0] + bv0, p1 = acc[mf][nf][1] + bv1;
            float p2 = acc[mf][nf][2] + bv0, p3 = acc[mf][nf][3] + bv1;
            if (p.out) {
                float2 lo_pair, hi_pair;
                lo_pair.x = p0; lo_pair.y = p1;
                hi_pair.x = p2; hi_pair.y = p3;
                *(float2*)(p.out + (size_t)b1 * p.sB + (size_t)s1 * p.sS + (size_t)h * p.sH + d) = lo_pair;
                *(float2*)(p.out + (size_t)b2 * p.sB + (size_t)s2 * p.sS + (size_t)h * p.sH + d) = hi_pair;
            }
            if (p.oh) {
                size_t i1 = (size_t)b1 * s2B + (size_t)s1 * s2S + (size_t)h * s2H + d;
                size_t i2 = (size_t)b2 * s2B + (size_t)s2 * s2S + (size_t)h * s2H + d;
                *(uint32_t*)(p.oh + i1) = pack_h(p0, p1);
                *(uint32_t*)(p.oh + i2) = pack_h(p2, p3);
            }
        }
    }
    #undef ISSUE
}

// ---------------------------------------------------------------------------
// Tensor-core flash attention (fp16, causal, exp2 softmax).
// 128 q/CTA, 4 warps, KV double-buffered, single sync per k-tile.
// ---------------------------------------------------------------------------
#define LOG2E      1.4426950408889634f
#define ASCALE     (0.125f * LOG2E)
#define AMASK      (-10000.0f * LOG2E)

#define QT_BYTES   (128 * 144)
#define KVMAT      (64 * 144)
#define KVSTG      (2 * KVMAT)              // K|V = 18432
#define ATT_SMEM   (QT_BYTES + 2 * KVSTG)   // 55296

__global__ __launch_bounds__(128) void attn_mma_kernel(
    const __half* __restrict__ Qhg,
    const __half* __restrict__ Khg, const __half* __restrict__ Vhg,
    __half* __restrict__ Ohg)
{
    extern __shared__ char sm[];
    const uint32_t sb  = smem_u32(sm);
    const uint32_t sQh = sb;
    const uint32_t sKV = sb + QT_BYTES;

    const int tid = threadIdx.x, lane = tid & 31, wid = tid >> 5;
    const int bidx = blockIdx.x;
    const int qblk = (S_ / 128 - 1) - (bidx >> 5);
    const int hb = bidx & 31;
    const int h = hb & 15, b = hb >> 4;
    const int q0 = qblk * 128;
    const int wrow = wid * 32;
    const int g = lane >> 2, tig = lane & 3;

    const size_t hoff = ((size_t)(b * H_ + h) * S_) * DH_;
    const __half* qh_p = Qhg + hoff + (size_t)q0 * DH_;
    const __half* kh_p = Khg + hoff;
    const __half* vh_p = Vhg + hoff;

    #define KV_ISSUE(k0v, st) do { \
        const uint32_t sst = sKV + (st) * KVSTG; \
        _Pragma("unroll") \
        for (int i = 0; i < 8; i++) { \
            int idx = tid + i * 128; \
            int mat = idx >> 9, rem = idx & 511, row = rem >> 3, c = rem & 7; \
            const __half* gp = (mat ? vh_p : kh_p) + (size_t)((k0v) + row) * 64 + c * 8; \
            uint32_t sa = sst + mat * KVMAT + row * 144 + c * 16; \
            CP_ASYNC16(sa, gp); \
        } \
        CP_COMMIT(); \
    } while (0)

    const int ktmax = 2 * qblk + 1;

    // ---- prologue: Q + KV0 in one commit group ----
    #pragma unroll
    for (int i = 0; i < 8; i++) {
        int idx = tid + i * 128;
        int row = idx >> 3, c = idx & 7;
        CP_ASYNC16(sQh + row * 144 + c * 16, qh_p + row * 64 + c * 8);
    }
    KV_ISSUE(0, 0);
    CP_WAITN(0);
    __syncthreads();

    // ---- hoist Q fragments ----
    uint32_t qf[4][2][4];
    #pragma unroll
    for (int kc = 0; kc < 4; kc++)
        #pragma unroll
        for (int mf = 0; mf < 2; mf++) {
            uint32_t ra = (uint32_t)(wrow + mf * 16 + (lane & 15)) * 144
                          + kc * 32 + (lane >> 4) * 16;
            LDMX4(qf[kc][mf], sQh + ra);
        }

    float o[2][8][4] = {};
    float m_run[2][2] = {{-1e30f, -1e30f}, {-1e30f, -1e30f}};
    float l_run[2][2] = {};

    for (int kt = 0; kt <= ktmax; kt++) {
        const int k0 = kt * 64;
        const uint32_t sst = sKV + (kt & 1) * KVSTG;
        const uint32_t sKh = sst, sVh = sst + KVMAT;

        if (kt < ktmax) KV_ISSUE(k0 + 64, (kt + 1) & 1);

        // ---- S = Q K^T ----
        float s[2][8][4] = {};
        #pragma unroll
        for (int kc = 0; kc < 4; kc++) {
            #pragma unroll
            for (int ng = 0; ng < 4; ng++) {
                uint32_t rb = (uint32_t)(ng * 16 + ((lane >> 4) << 3) + (lane & 7)) * 144
                              + kc * 32 + ((lane >> 3) & 1) * 16;
                uint32_t kh[4];
                LDMX4(kh, sKh + rb);
                #pragma unroll
                for (int mf = 0; mf < 2; mf++) {
                    MMA_F16(s[mf][2*ng],   qf[kc][mf], kh[0], kh[1]);
                    MMA_F16(s[mf][2*ng+1], qf[kc][mf], kh[2], kh[3]);
                }
            }
        }

        // ---- scale + causal mask (log2 domain) ----
        const bool maskw = (k0 + 63) > (q0 + wrow);
        #pragma unroll
        for (int mf = 0; mf < 2; mf++)
            #pragma unroll
            for (int nf = 0; nf < 8; nf++)
                #pragma unroll
                for (int r = 0; r < 4; r++) {
                    float v = s[mf][nf][r] * ASCALE;
                    if (maskw) {
                        int qi = q0 + wrow + mf * 16 + g + ((r >= 2) ? 8 : 0);
                        int kj = k0 + nf * 8 + tig * 2 + (r & 1);
                        if (kj > qi) v += AMASK;
                    }
                    s[mf][nf][r] = v;
                }

        // ---- online softmax (exp2) ----
        float alpha[2][2];
        #pragma unroll
        for (int mf = 0; mf < 2; mf++)
            #pragma unroll
            for (int h2 = 0; h2 < 2; h2++) {
                float mx = -1e30f;
                #pragma unroll
                for (int nf = 0; nf < 8; nf++)
                    mx = fmaxf(mx, fmaxf(s[mf][nf][h2*2], s[mf][nf][h2*2+1]));
                mx = fmaxf(mx, __shfl_xor_sync(0xffffffffu, mx, 1));
                mx = fmaxf(mx, __shfl_xor_sync(0xffffffffu, mx, 2));
                float mn = fmaxf(m_run[mf][h2], mx);
                float sum = 0.f;
                #pragma unroll
                for (int nf = 0; nf < 8; nf++) {
                    float p0 = exp2f(s[mf][nf][h2*2]   - mn);
                    float p1 = exp2f(s[mf][nf][h2*2+1] - mn);
                    s[mf][nf][h2*2]   = p0;
                    s[mf][nf][h2*2+1] = p1;
                    sum += p0 + p1;
                }
                sum += __shfl_xor_sync(0xffffffffu, sum, 1);
                sum += __shfl_xor_sync(0xffffffffu, sum, 2);
                float a = exp2f(m_run[mf][h2] - mn);
                alpha[mf][h2] = a;
                m_run[mf][h2] = mn;
                l_run[mf][h2] = l_run[mf][h2] * a + sum;
            }

        #pragma unroll
        for (int mf = 0; mf < 2; mf++)
            #pragma unroll
            for (int nf = 0; nf < 8; nf++) {
                o[mf][nf][0] *= alpha[mf][0];
                o[mf][nf][1] *= alpha[mf][0];
                o[mf][nf][2] *= alpha[mf][1];
                o[mf][nf][3] *= alpha[mf][1];
            }

        // ---- O += P V ----
        #pragma unroll
        for (int kc = 0; kc < 4; kc++) {
            uint32_t ph[2][4];
            #pragma unroll
            for (int mf = 0; mf < 2; mf++) {
                ph[mf][0] = pack_h(s[mf][2*kc][0],   s[mf][2*kc][1]);
                ph[mf][1] = pack_h(s[mf][2*kc][2],   s[mf][2*kc][3]);
                ph[mf][2] = pack_h(s[mf][2*kc+1][0], s[mf][2*kc+1][1]);
                ph[mf][3] = pack_h(s[mf][2*kc+1][2], s[mf][2*kc+1][3]);
            }
            #pragma unroll
            for (int ng = 0; ng < 4; ng++) {
                uint32_t rv = (uint32_t)(kc * 16 + ((lane >> 3) & 1) * 8 + (lane & 7)) * 144
                              + ng * 32 + (lane >> 4) * 16;
                uint32_t vh[4];
                LDMX4T(vh, sVh + rv);
                #pragma unroll
                for (int mf = 0; mf < 2; mf++) {
                    MMA_F16(o[mf][2*ng],   ph[mf], vh[0], vh[1]);
                    MMA_F16(o[mf][2*ng+1], ph[mf], vh[2], vh[3]);
                }
            }
        }

        if (kt < ktmax) { CP_WAITN(0); __syncthreads(); }
    }

    // ---- epilogue: ctx -> fp16 into GEMM A buffer ----
    float inv[2][2];
    #pragma unroll
    for (int mf = 0; mf < 2; mf++) {
        inv[mf][0] = 1.f / l_run[mf][0];
        inv[mf][1] = 1.f / l_run[mf][1];
    }
    #pragma unroll
    for (int mf = 0; mf < 2; mf++) {
        const int r0 = q0 + wrow + mf * 16 + g;
        const size_t m1 = (size_t)b * 2048 + r0;
        const size_t m2 = m1 + 8;
        #pragma unroll
        for (int nf = 0; nf < 8; nf++) {
            const int col = h * 64 + nf * 8 + tig * 2;
            *(uint32_t*)(Ohg + m1 * 1024 + col) =
                pack_h(o[mf][nf][0] * inv[mf][0], o[mf][nf][1] * inv[mf][0]);
            *(uint32_t*)(Ohg + m2 * 1024 + col) =
                pack_h(o[mf][nf][2] * inv[mf][1], o[mf][nf][3] * inv[mf][1]);
        }
    }
    #undef KV_ISSUE
}

// ---------------------------------------------------------------------------
extern "C" void kernel_launch(void* const* d_in, const int* in_sizes, int n_in,
                              void* d_out, int out_size)
{
    const float* q  = (const float*)d_in[0];
    const float* k  = (const float*)d_in[1];
    const float* v  = (const float*)d_in[2];
    const float* Wq = (const float*)d_in[4];
    const float* bq = (const float*)d_in[5];
    const float* Wk = (const float*)d_in[6];
    const float* bk = (const float*)d_in[7];
    const float* Wv = (const float*)d_in[8];
    const float* bv = (const float*)d_in[9];
    const float* Wo = (const float*)d_in[10];
    const float* bo = (const float*)d_in[11];

    float* out = (float*)d_out;                       // [B,S,D]
    float* present = out + (size_t)B_ * S_ * D_;      // [B,2,H,S,DH]

    __half *xh0, *xh1, *xh2;
    __half *wh0, *wh1, *wh2, *wh3;
    __half *qbh, *kbh, *vbh;
    cudaGetSymbolAddress((void**)&xh0, g_xh);
    cudaGetSymbolAddress((void**)&wh0, g_wh);
    cudaGetSymbolAddress((void**)&qbh, g_qbh);
    cudaGetSymbolAddress((void**)&kbh, g_kbh);
    cudaGetSymbolAddress((void**)&vbh, g_vbh);
    const size_t XSZ = (size_t)4096 * 1024, WSZ = (size_t)1024 * 1024;
    xh1 = xh0 + XSZ; xh2 = xh0 + 2 * XSZ;
    wh1 = wh0 + WSZ; wh2 = wh0 + 2 * WSZ; wh3 = wh0 + 3 * WSZ;

    const long sB_head = (long)H_ * S_ * DH_;
    const long sH_head = (long)S_ * DH_;

    cudaFuncSetAttribute(gemm_mma_kernel, cudaFuncAttributeMaxDynamicSharedMemorySize, GEMM_SMEM);
    cudaFuncSetAttribute(attn_mma_kernel, cudaFuncAttributeMaxDynamicSharedMemorySize, ATT_SMEM);

    // fused prep
    PrepArgs pa = {q, k, v, Wq, Wk, Wv, Wo, xh0, xh1, xh2};
    prep_kernel<<<16384, 256>>>(pa);

    // fused Q/K/V projections
    GB3 P;
    P.g[0] = {xh0, wh0, bq, nullptr, 0, 0, 0, qbh};
    P.g[1] = {xh1, wh1, bk, present, 2 * sB_head, (long)DH_, sH_head, kbh};
    P.g[2] = {xh2, wh2, bv, present + (size_t)sB_head,
              2 * sB_head, (long)DH_, sH_head, vbh};
    gemm_mma_kernel<<<dim3(8, 32, 3), 256, GEMM_SMEM>>>(P);

    // attention: ctx written as fp16 into g_xh[0]
    attn_mma_kernel<<<(S_ / 128) * H_ * B_, 128, ATT_SMEM>>>(qbh, kbh, vbh, xh0);

    // output projection: out = ctx @ Wo + bo
    GB3 PO;
    PO.g[0] = {xh0, wh3, bo, out, (long)S_ * D_, (long)D_, (long)DH_, nullptr};
    PO.g[1] = PO.g[0];
    PO.g[2] = PO.g[0];
    gemm_mma_kernel<<<dim3(8, 32, 1), 256, GEMM_SMEM>>>(PO);
}

// round 16
// speedup vs baseline: 2.5012x; 1.0298x over previous
#include <cuda_runtime.h>
#include <cuda_fp16.h>
#include <cstdint>

#define B_  2
#define S_  2048
#define D_  1024
#define H_  16
#define DH_ 64

// ---------------------------------------------------------------------------
// Scratch (device globals — no allocation allowed)
// ---------------------------------------------------------------------------
__device__ __half g_xh[3][(size_t)4096 * 1024];  // fp16 of X (q,k,v); [0] reused for ctx
__device__ __half g_wh[4][(size_t)1024 * 1024];  // fp16 of W^T (q,k,v,o)
__device__ __half g_qbh[(size_t)B_ * H_ * S_ * DH_];  // Q fp16 [B,H,S,DH]
__device__ __half g_kbh[(size_t)B_ * H_ * S_ * DH_];  // K fp16
__device__ __half g_vbh[(size_t)B_ * H_ * S_ * DH_];  // V fp16

// ---------------------------------------------------------------------------
__device__ __forceinline__ uint32_t smem_u32(const void* p) {
    uint32_t a;
    asm("{ .reg .u64 t; cvta.to.shared.u64 t, %1; cvt.u32.u64 %0, t; }" : "=r"(a) : "l"(p));
    return a;
}

#define LDMX4(r, addr) \
    asm volatile("ldmatrix.sync.aligned.m8n8.x4.shared.b16 {%0,%1,%2,%3}, [%4];" \
        : "=r"((r)[0]), "=r"((r)[1]), "=r"((r)[2]), "=r"((r)[3]) : "r"(addr))

#define LDMX4T(r, addr) \
    asm volatile("ldmatrix.sync.aligned.m8n8.x4.trans.shared.b16 {%0,%1,%2,%3}, [%4];" \
        : "=r"((r)[0]), "=r"((r)[1]), "=r"((r)[2]), "=r"((r)[3]) : "r"(addr))

#define MMA_F16(d, a, b0, b1) \
    asm volatile("mma.sync.aligned.m16n8k16.row.col.f32.f16.f16.f32 " \
        "{%0,%1,%2,%3}, {%4,%5,%6,%7}, {%8,%9}, {%0,%1,%2,%3};" \
        : "+f"((d)[0]), "+f"((d)[1]), "+f"((d)[2]), "+f"((d)[3]) \
        : "r"((a)[0]), "r"((a)[1]), "r"((a)[2]), "r"((a)[3]), "r"(b0), "r"(b1))

#define CP_ASYNC16(sa, gp) \
    asm volatile("cp.async.cg.shared.global [%0], [%1], 16;" :: "r"(sa), "l"(gp))
#define CP_COMMIT() asm volatile("cp.async.commit_group;" ::: "memory")
#define CP_WAITN(n) asm volatile("cp.async.wait_group %0;" :: "n"(n) : "memory")

__device__ __forceinline__ uint32_t pack_h(float v0, float v1) {
    __half2 h2 = __floats2half2_rn(v0, v1);
    return *reinterpret_cast<uint32_t*>(&h2);
}

// ---------------------------------------------------------------------------
// Fused prep: blocks [0,12288) = fp16 casts of q,k,v;
//             blocks [12288,16384) = transpose + fp16 cast of the 4 weights.
// ---------------------------------------------------------------------------
struct PrepArgs {
    const float *q, *k, *v, *W0, *W1, *W2, *W3;
    __half *xh0, *xh1, *xh2;
};

__global__ __launch_bounds__(256) void prep_kernel(PrepArgs a)
{
    __shared__ float ts[32][33];
    const int bid = blockIdx.x;
    if (bid < 12288) {
        const int z = bid >> 12;
        const int blk = bid & 4095;
        const float* x = (z == 0) ? a.q : (z == 1) ? a.k : a.v;
        __half* hi = (z == 0) ? a.xh0 : (z == 1) ? a.xh1 : a.xh2;
        int i = blk * 256 + threadIdx.x;
        float4 v4 = ((const float4*)x)[i];
        ((uint32_t*)hi)[i * 2]     = pack_h(v4.x, v4.y);
        ((uint32_t*)hi)[i * 2 + 1] = pack_h(v4.z, v4.w);
    } else {
        const int j = bid - 12288;
        const int z = j >> 10;
        const int r = j & 1023;
        const int kb = (r >> 5) << 5, nb = (r & 31) << 5;
        const float* W = (z == 0) ? a.W0 : (z == 1) ? a.W1 : (z == 2) ? a.W2 : a.W3;
        __half* th = g_wh[z];
        int tx = threadIdx.x & 31, ty = threadIdx.x >> 5;
        #pragma unroll
        for (int jj = 0; jj < 4; jj++)
            ts[ty + jj * 8][tx] = W[(size_t)(kb + ty + jj * 8) * 1024 + nb + tx];
        __syncthreads();
        #pragma unroll
        for (int jj = 0; jj < 4; jj++) {
            int n = nb + ty + jj * 8, kk = kb + tx;
            th[(size_t)n * 1024 + kk] = __float2half_rn(ts[tx][ty + jj * 8]);
        }
    }
}

// ---------------------------------------------------------------------------
// fp16 mma.sync GEMM: out = X @ W + bias.
// CTA 128x128, K-tile 64 (4 ks-subtiles per barrier), 2-stage, 8 warps
// (64x32), single sync per k-tile. Stage = 36,864 B -> 2 CTAs/SM retained.
// ---------------------------------------------------------------------------
struct GB {
    const __half *Ah, *Bh;
    const float* bias;
    float* out; long sB, sS, sH;
    __half *oh;
};
struct GB3 { GB g[3]; };

#define SA_STRIDE 144                       // 128B data + 16B pad
#define MAT_BYTES (128 * SA_STRIDE)         // 18432
#define STG_BYTES (2 * MAT_BYTES)           // 36864: Ah|Bh
#define GEMM_SMEM (2 * STG_BYTES)           // 73728

__global__ __launch_bounds__(256) void gemm_mma_kernel(GB3 P)
{
    const GB p = P.g[blockIdx.z];
    extern __shared__ char sm[];
    const uint32_t sbase = smem_u32(sm);
    const int tid = threadIdx.x, lane = tid & 31, wid = tid >> 5;
    const int wm = wid & 1, wn = wid >> 1;
    const int m0 = blockIdx.y * 128, n0 = blockIdx.x * 128;

    float acc[4][4][4] = {};

    const int arow  = lane & 15;
    const int akoff = (lane >> 4) * 16;
    const int brow  = ((lane >> 4) << 3) | (lane & 7);
    const int bkoff = ((lane >> 3) & 1) * 16;

    // per stage: 2 mats x 128 rows x 8 chunks of 16B = 2048 chunks; 8/thread
    #define ISSUE(t) do { \
        const int k0i = (t) * 64; \
        const uint32_t sdst = sbase + ((t) & 1) * STG_BYTES; \
        _Pragma("unroll") \
        for (int i = 0; i < 8; i++) { \
            int idx = tid + i * 256; \
            int mat = idx >> 10, rem = idx & 1023; \
            int row = rem >> 3, c = rem & 7; \
            const __half* gp = (mat ? p.Bh + (size_t)(n0 + row) * 1024 \
                                    : p.Ah + (size_t)(m0 + row) * 1024) + k0i + c * 8; \
            uint32_t sa = sdst + mat * MAT_BYTES + row * SA_STRIDE + c * 16; \
            CP_ASYNC16(sa, gp); \
        } \
        CP_COMMIT(); \
    } while (0)

    ISSUE(0);
    CP_WAITN(0);
    __syncthreads();

    for (int t = 0; t < 16; t++) {
        if (t < 15) ISSUE(t + 1);

        const uint32_t s0  = sbase + (t & 1) * STG_BYTES;
        const uint32_t pAh = s0;
        const uint32_t pBh = s0 + MAT_BYTES;

        #pragma unroll
        for (int ks = 0; ks < 4; ks++) {
            uint32_t ah[4][4];
            #pragma unroll
            for (int mf = 0; mf < 4; mf++) {
                uint32_t ra = (uint32_t)(wm * 64 + mf * 16 + arow) * SA_STRIDE + ks * 32 + akoff;
                LDMX4(ah[mf], pAh + ra);
            }
            uint32_t bh[2][4];
            #pragma unroll
            for (int ng = 0; ng < 2; ng++) {
                uint32_t rb = (uint32_t)(wn * 32 + ng * 16 + brow) * SA_STRIDE + ks * 32 + bkoff;
                LDMX4(bh[ng], pBh + rb);
            }
            #pragma unroll
            for (int mf = 0; mf < 4; mf++)
                #pragma unroll
                for (int nf = 0; nf < 4; nf++) {
                    const uint32_t* bhp = &bh[nf >> 1][(nf & 1) * 2];
                    MMA_F16(acc[mf][nf], ah[mf], bhp[0], bhp[1]);
                }
        }

        if (t < 15) { CP_WAITN(0); __syncthreads(); }
    }

    // ---- epilogue ----
    const int g = lane >> 2, tig = lane & 3;
    const long s2S = DH_, s2H = (long)S_ * DH_, s2B = (long)H_ * S_ * DH_;
    #pragma unroll
    for (int mf = 0; mf < 4; mf++) {
        const int mA = m0 + wm * 64 + mf * 16 + g;
        const int b1 = mA >> 11, s1 = mA & 2047;
        const int b2 = (mA + 8) >> 11, s2 = (mA + 8) & 2047;
        #pragma unroll
        for (int nf = 0; nf < 4; nf++) {
            const int n = n0 + wn * 32 + nf * 8 + tig * 2;
            const int h = n >> 6, d = n & 63;
            const float bv0 = __ldg(p.bias + n), bv1 = __ldg(p.bias + n + 1);
            float p0 = acc[mf][nf][0] + bv0, p1 = acc[mf][nf][1] + bv1;
            float p2 = acc[mf][nf][2] + bv0, p3 = acc[mf][nf][3] + bv1;
            if (p.out) {
                float2 lo_pair, hi_pair;
                lo_pair.x = p0; lo_pair.y = p1;
                hi_pair.x = p2; hi_pair.y = p3;
                *(float2*)(p.out + (size_t)b1 * p.sB + (size_t)s1 * p.sS + (size_t)h * p.sH + d) = lo_pair;
                *(float2*)(p.out + (size_t)b2 * p.sB + (size_t)s2 * p.sS + (size_t)h * p.sH + d) = hi_pair;
            }
            if (p.oh) {
                size_t i1 = (size_t)b1 * s2B + (size_t)s1 * s2S + (size_t)h * s2H + d;
                size_t i2 = (size_t)b2 * s2B + (size_t)s2 * s2S + (size_t)h * s2H + d;
                *(uint32_t*)(p.oh + i1) = pack_h(p0, p1);
                *(uint32_t*)(p.oh + i2) = pack_h(p2, p3);
            }
        }
    }
    #undef ISSUE
}

// ---------------------------------------------------------------------------
// Tensor-core flash attention (fp16, causal, exp2 softmax).
// 128 q/CTA, 4 warps, KV double-buffered, single sync per k-tile. (R15)
// ---------------------------------------------------------------------------
#define LOG2E      1.4426950408889634f
#define ASCALE     (0.125f * LOG2E)
#define AMASK      (-10000.0f * LOG2E)

#define QT_BYTES   (128 * 144)
#define KVMAT      (64 * 144)
#define KVSTG      (2 * KVMAT)              // K|V = 18432
#define ATT_SMEM   (QT_BYTES + 2 * KVSTG)   // 55296

__global__ __launch_bounds__(128) void attn_mma_kernel(
    const __half* __restrict__ Qhg,
    const __half* __restrict__ Khg, const __half* __restrict__ Vhg,
    __half* __restrict__ Ohg)
{
    extern __shared__ char sm[];
    const uint32_t sb  = smem_u32(sm);
    const uint32_t sQh = sb;
    const uint32_t sKV = sb + QT_BYTES;

    const int tid = threadIdx.x, lane = tid & 31, wid = tid >> 5;
    const int bidx = blockIdx.x;
    const int qblk = (S_ / 128 - 1) - (bidx >> 5);
    const int hb = bidx & 31;
    const int h = hb & 15, b = hb >> 4;
    const int q0 = qblk * 128;
    const int wrow = wid * 32;
    const int g = lane >> 2, tig = lane & 3;

    const size_t hoff = ((size_t)(b * H_ + h) * S_) * DH_;
    const __half* qh_p = Qhg + hoff + (size_t)q0 * DH_;
    const __half* kh_p = Khg + hoff;
    const __half* vh_p = Vhg + hoff;

    #define KV_ISSUE(k0v, st) do { \
        const uint32_t sst = sKV + (st) * KVSTG; \
        _Pragma("unroll") \
        for (int i = 0; i < 8; i++) { \
            int idx = tid + i * 128; \
            int mat = idx >> 9, rem = idx & 511, row = rem >> 3, c = rem & 7; \
            const __half* gp = (mat ? vh_p : kh_p) + (size_t)((k0v) + row) * 64 + c * 8; \
            uint32_t sa = sst + mat * KVMAT + row * 144 + c * 16; \
            CP_ASYNC16(sa, gp); \
        } \
        CP_COMMIT(); \
    } while (0)

    const int ktmax = 2 * qblk + 1;

    #pragma unroll
    for (int i = 0; i < 8; i++) {
        int idx = tid + i * 128;
        int row = idx >> 3, c = idx & 7;
        CP_ASYNC16(sQh + row * 144 + c * 16, qh_p + row * 64 + c * 8);
    }
    KV_ISSUE(0, 0);
    CP_WAITN(0);
    __syncthreads();

    uint32_t qf[4][2][4];
    #pragma unroll
    for (int kc = 0; kc < 4; kc++)
        #pragma unroll
        for (int mf = 0; mf < 2; mf++) {
            uint32_t ra = (uint32_t)(wrow + mf * 16 + (lane & 15)) * 144
                          + kc * 32 + (lane >> 4) * 16;
            LDMX4(qf[kc][mf], sQh + ra);
        }

    float o[2][8][4] = {};
    float m_run[2][2] = {{-1e30f, -1e30f}, {-1e30f, -1e30f}};
    float l_run[2][2] = {};

    for (int kt = 0; kt <= ktmax; kt++) {
        const int k0 = kt * 64;
        const uint32_t sst = sKV + (kt & 1) * KVSTG;
        const uint32_t sKh = sst, sVh = sst + KVMAT;

        if (kt < ktmax) KV_ISSUE(k0 + 64, (kt + 1) & 1);

        float s[2][8][4] = {};
        #pragma unroll
        for (int kc = 0; kc < 4; kc++) {
            #pragma unroll
            for (int ng = 0; ng < 4; ng++) {
                uint32_t rb = (uint32_t)(ng * 16 + ((lane >> 4) << 3) + (lane & 7)) * 144
                              + kc * 32 + ((lane >> 3) & 1) * 16;
                uint32_t kh[4];
                LDMX4(kh, sKh + rb);
                #pragma unroll
                for (int mf = 0; mf < 2; mf++) {
                    MMA_F16(s[mf][2*ng],   qf[kc][mf], kh[0], kh[1]);
                    MMA_F16(s[mf][2*ng+1], qf[kc][mf], kh[2], kh[3]);
                }
            }
        }

        const bool maskw = (k0 + 63) > (q0 + wrow);
        #pragma unroll
        for (int mf = 0; mf < 2; mf++)
            #pragma unroll
            for (int nf = 0; nf < 8; nf++)
                #pragma unroll
                for (int r = 0; r < 4; r++) {
                    float v = s[mf][nf][r] * ASCALE;
                    if (maskw) {
                        int qi = q0 + wrow + mf * 16 + g + ((r >= 2) ? 8 : 0);
                        int kj = k0 + nf * 8 + tig * 2 + (r & 1);
                        if (kj > qi) v += AMASK;
                    }
                    s[mf][nf][r] = v;
                }

        float alpha[2][2];
        #pragma unroll
        for (int mf = 0; mf < 2; mf++)
            #pragma unroll
            for (int h2 = 0; h2 < 2; h2++) {
                float mx = -1e30f;
                #pragma unroll
                for (int nf = 0; nf < 8; nf++)
                    mx = fmaxf(mx, fmaxf(s[mf][nf][h2*2], s[mf][nf][h2*2+1]));
                mx = fmaxf(mx, __shfl_xor_sync(0xffffffffu, mx, 1));
                mx = fmaxf(mx, __shfl_xor_sync(0xffffffffu, mx, 2));
                float mn = fmaxf(m_run[mf][h2], mx);
                float sum = 0.f;
                #pragma unroll
                for (int nf = 0; nf < 8; nf++) {
                    float p0 = exp2f(s[mf][nf][h2*2]   - mn);
                    float p1 = exp2f(s[mf][nf][h2*2+1] - mn);
                    s[mf][nf][h2*2]   = p0;
                    s[mf][nf][h2*2+1] = p1;
                    sum += p0 + p1;
                }
                sum += __shfl_xor_sync(0xffffffffu, sum, 1);
                sum += __shfl_xor_sync(0xffffffffu, sum, 2);
                float a = exp2f(m_run[mf][h2] - mn);
                alpha[mf][h2] = a;
                m_run[mf][h2] = mn;
                l_run[mf][h2] = l_run[mf][h2] * a + sum;
            }

        #pragma unroll
        for (int mf = 0; mf < 2; mf++)
            #pragma unroll
            for (int nf = 0; nf < 8; nf++) {
                o[mf][nf][0] *= alpha[mf][0];
                o[mf][nf][1] *= alpha[mf][0];
                o[mf][nf][2] *= alpha[mf][1];
                o[mf][nf][3] *= alpha[mf][1];
            }

        #pragma unroll
        for (int kc = 0; kc < 4; kc++) {
            uint32_t ph[2][4];
            #pragma unroll
            for (int mf = 0; mf < 2; mf++) {
                ph[mf][0] = pack_h(s[mf][2*kc][0],   s[mf][2*kc][1]);
                ph[mf][1] = pack_h(s[mf][2*kc][2],   s[mf][2*kc][3]);
                ph[mf][2] = pack_h(s[mf][2*kc+1][0], s[mf][2*kc+1][1]);
                ph[mf][3] = pack_h(s[mf][2*kc+1][2], s[mf][2*kc+1][3]);
            }
            #pragma unroll
            for (int ng = 0; ng < 4; ng++) {
                uint32_t rv = (uint32_t)(kc * 16 + ((lane >> 3) & 1) * 8 + (lane & 7)) * 144
                              + ng * 32 + (lane >> 4) * 16;
                uint32_t vh[4];
                LDMX4T(vh, sVh + rv);
                #pragma unroll
                for (int mf = 0; mf < 2; mf++) {
                    MMA_F16(o[mf][2*ng],   ph[mf], vh[0], vh[1]);
                    MMA_F16(o[mf][2*ng+1], ph[mf], vh[2], vh[3]);
                }
            }
        }

        if (kt < ktmax) { CP_WAITN(0); __syncthreads(); }
    }

    float inv[2][2];
    #pragma unroll
    for (int mf = 0; mf < 2; mf++) {
        inv[mf][0] = 1.f / l_run[mf][0];
        inv[mf][1] = 1.f / l_run[mf][1];
    }
    #pragma unroll
    for (int mf = 0; mf < 2; mf++) {
        const int r0 = q0 + wrow + mf * 16 + g;
        const size_t m1 = (size_t)b * 2048 + r0;
        const size_t m2 = m1 + 8;
        #pragma unroll
        for (int nf = 0; nf < 8; nf++) {
            const int col = h * 64 + nf * 8 + tig * 2;
            *(uint32_t*)(Ohg + m1 * 1024 + col) =
                pack_h(o[mf][nf][0] * inv[mf][0], o[mf][nf][1] * inv[mf][0]);
            *(uint32_t*)(Ohg + m2 * 1024 + col) =
                pack_h(o[mf][nf][2] * inv[mf][1], o[mf][nf][3] * inv[mf][1]);
        }
    }
    #undef KV_ISSUE
}

// ---------------------------------------------------------------------------
extern "C" void kernel_launch(void* const* d_in, const int* in_sizes, int n_in,
                              void* d_out, int out_size)
{
    const float* q  = (const float*)d_in[0];
    const float* k  = (const float*)d_in[1];
    const float* v  = (const float*)d_in[2];
    const float* Wq = (const float*)d_in[4];
    const float* bq = (const float*)d_in[5];
    const float* Wk = (const float*)d_in[6];
    const float* bk = (const float*)d_in[7];
    const float* Wv = (const float*)d_in[8];
    const float* bv = (const float*)d_in[9];
    const float* Wo = (const float*)d_in[10];
    const float* bo = (const float*)d_in[11];

    float* out = (float*)d_out;                       // [B,S,D]
    float* present = out + (size_t)B_ * S_ * D_;      // [B,2,H,S,DH]

    __half *xh0, *xh1, *xh2;
    __half *wh0, *wh1, *wh2, *wh3;
    __half *qbh, *kbh, *vbh;
    cudaGetSymbolAddress((void**)&xh0, g_xh);
    cudaGetSymbolAddress((void**)&wh0, g_wh);
    cudaGetSymbolAddress((void**)&qbh, g_qbh);
    cudaGetSymbolAddress((void**)&kbh, g_kbh);
    cudaGetSymbolAddress((void**)&vbh, g_vbh);
    const size_t XSZ = (size_t)4096 * 1024, WSZ = (size_t)1024 * 1024;
    xh1 = xh0 + XSZ; xh2 = xh0 + 2 * XSZ;
    wh1 = wh0 + WSZ; wh2 = wh0 + 2 * WSZ; wh3 = wh0 + 3 * WSZ;

    const long sB_head = (long)H_ * S_ * DH_;
    const long sH_head = (long)S_ * DH_;

    cudaFuncSetAttribute(gemm_mma_kernel, cudaFuncAttributeMaxDynamicSharedMemorySize, GEMM_SMEM);
    cudaFuncSetAttribute(attn_mma_kernel, cudaFuncAttributeMaxDynamicSharedMemorySize, ATT_SMEM);

    // fused prep
    PrepArgs pa = {q, k, v, Wq, Wk, Wv, Wo, xh0, xh1, xh2};
    prep_kernel<<<16384, 256>>>(pa);

    // fused Q/K/V projections
    GB3 P;
    P.g[0] = {xh0, wh0, bq, nullptr, 0, 0, 0, qbh};
    P.g[1] = {xh1, wh1, bk, present, 2 * sB_head, (long)DH_, sH_head, kbh};
    P.g[2] = {xh2, wh2, bv, present + (size_t)sB_head,
              2 * sB_head, (long)DH_, sH_head, vbh};
    gemm_mma_kernel<<<dim3(8, 32, 3), 256, GEMM_SMEM>>>(P);

    // attention: ctx written as fp16 into g_xh[0]
    attn_mma_kernel<<<(S_ / 128) * H_ * B_, 128, ATT_SMEM>>>(qbh, kbh, vbh, xh0);

    // output projection: out = ctx @ Wo + bo
    GB3 PO;
    PO.g[0] = {xh0, wh3, bo, out, (long)S_ * D_, (long)D_, (long)DH_, nullptr};
    PO.g[1] = PO.g[0];
    PO.g[2] = PO.g[0];
    gemm_mma_kernel<<<dim3(8, 32, 1), 256, GEMM_SMEM>>>(PO);
}